// round 7
// baseline (speedup 1.0000x reference)
#include <cuda_runtime.h>
#include <cuda_bf16.h>
#include <math.h>
#include <stdint.h>

// ---------------- problem constants ----------------
#define BB 64
#define SS 512
#define HH 768
#define NN 128
#define EE 1024
#define GHD 128
#define FHD 256
#define BNN (BB*NN)          // 8192

typedef __nv_bfloat16 bf16;

// ---------------- device scratch (no allocation allowed) ----------------
__device__ float g_gate[BB*SS];
__device__ int   g_cnt[BNN];
__device__ int   g_perm[BB*SS];
__device__ float g_wsort[BB*SS];          // gate * inv_cnt, sorted order
__device__ int   g_soff[BB*(NN+1)];
__device__ bf16  g_nf[BNN*HH];            // node features bf16, 12.6 MB
__device__ bf16  g_A[BB*NN*NN];           // normalized adjacency bf16
__device__ bf16  g_W1t[GHD*HH];           // W1 transposed [n][k] bf16
__device__ bf16  g_W2t[GHD*GHD];          // W2 transposed [n][k] bf16
__device__ bf16  g_H1t[BB*GHD*NN];        // H1 transposed per batch [feat][node]
__device__ bf16  g_X1[BNN*GHD];           // X1 normal [row][feat]
__device__ bf16  g_H2t[BB*GHD*NN];        // H2 transposed per batch
__device__ float g_pooled[BB*GHD];

// ---------------- bf16 mma m16n8k16 ----------------
__device__ __forceinline__ void mma_bf16(float* d, uint32_t a0, uint32_t a1,
                                         uint32_t a2, uint32_t a3,
                                         uint32_t b0, uint32_t b1) {
    asm volatile(
        "mma.sync.aligned.m16n8k16.row.col.f32.bf16.bf16.f32 "
        "{%0,%1,%2,%3}, {%4,%5,%6,%7}, {%8,%9}, {%0,%1,%2,%3};"
        : "+f"(d[0]), "+f"(d[1]), "+f"(d[2]), "+f"(d[3])
        : "r"(a0), "r"(a1), "r"(a2), "r"(a3), "r"(b0), "r"(b1));
}

// one BK=32 tile of MMA work; As/Bs are [64][40] bf16
__device__ __forceinline__ void mma_tile(const bf16 (*Ac)[40], const bf16 (*Bc)[40],
                                         float acc[2][4][4],
                                         int wm, int wn, int gid, int tig) {
#pragma unroll
    for (int kh = 0; kh < 32; kh += 16) {
        uint32_t a[2][4];
#pragma unroll
        for (int i2 = 0; i2 < 2; i2++) {
            int m = wm + i2*16;
            a[i2][0] = *(const uint32_t*)&Ac[m+gid  ][kh + 2*tig];
            a[i2][1] = *(const uint32_t*)&Ac[m+gid+8][kh + 2*tig];
            a[i2][2] = *(const uint32_t*)&Ac[m+gid  ][kh + 2*tig + 8];
            a[i2][3] = *(const uint32_t*)&Ac[m+gid+8][kh + 2*tig + 8];
        }
#pragma unroll
        for (int j = 0; j < 4; j++) {
            uint32_t b0 = *(const uint32_t*)&Bc[wn+j*8+gid][kh + 2*tig];
            uint32_t b1 = *(const uint32_t*)&Bc[wn+j*8+gid][kh + 2*tig + 8];
#pragma unroll
            for (int i2 = 0; i2 < 2; i2++)
                mma_bf16(acc[i2][j], a[i2][0], a[i2][1], a[i2][2], a[i2][3], b0, b1);
        }
    }
}

// ---------------- K1: token counts + zero pooled ----------------
__global__ void k_prep(const int* __restrict__ submap) {
    __shared__ int h[NN];
    int b = blockIdx.x, t = threadIdx.x;   // 128 threads
    if (t < NN) h[t] = 0;
    g_pooled[b*GHD + t] = 0.f;
    __syncthreads();
    for (int s = t; s < SS; s += blockDim.x)
        atomicAdd(&h[submap[b*SS + s]], 1);
    __syncthreads();
    if (t < NN) g_cnt[b*NN + t] = h[t];
}

// ---------------- K2: gate = sigmoid(lh . wr + br) ----------------
__global__ void k_gate(const float* __restrict__ lh, const float* __restrict__ wr,
                       const float* __restrict__ brp) {
    int warp = (blockIdx.x * blockDim.x + threadIdx.x) >> 5;
    int lane = threadIdx.x & 31;
    if (warp >= BB*SS) return;
    const float4* row = reinterpret_cast<const float4*>(lh + (size_t)warp * HH);
    const float4* w4  = reinterpret_cast<const float4*>(wr);
    float acc = 0.f;
#pragma unroll
    for (int i = 0; i < 6; i++) {
        float4 v = row[lane + i*32];
        float4 w = w4[lane + i*32];
        acc += v.x*w.x + v.y*w.y + v.z*w.z + v.w*w.w;
    }
#pragma unroll
    for (int o = 16; o; o >>= 1) acc += __shfl_xor_sync(0xffffffffu, acc, o);
    if (lane == 0) g_gate[warp] = 1.f / (1.f + __expf(-(acc + brp[0])));
}

// ---------------- K3: deterministic counting sort of tokens by node ----------------
__global__ __launch_bounds__(128)
void k_sort(const int* __restrict__ submap) {
    __shared__ int snode[SS];
    __shared__ int scnt[NN];
    __shared__ int soff[NN+1];
    int b = blockIdx.x, t = threadIdx.x;   // 128 threads
#pragma unroll
    for (int u = 0; u < 4; u++) snode[t + u*128] = submap[b*SS + t + u*128];
    scnt[t] = g_cnt[b*NN + t];
    __syncthreads();
    if (t == 0) {
        int run = 0;
        for (int n = 0; n < NN; n++) { soff[n] = run; run += scnt[n]; }
        soff[NN] = SS;
    }
    __syncthreads();
    {
        int o = soff[t];
        float inv = 1.f / (float)(scnt[t] < 1 ? 1 : scnt[t]);
        for (int s = 0; s < SS; s++) {
            if (snode[s] == t) {
                g_perm[b*SS + o]  = s;
                g_wsort[b*SS + o] = g_gate[b*SS + s] * inv;
                o++;
            }
        }
        g_soff[b*(NN+1) + t] = soff[t];
        if (t == 0) g_soff[b*(NN+1) + NN] = SS;
    }
}

// ---------------- K4 (PROFILED): sorted segment-mean, register accumulate -------
// grid (4 H-chunks of 192, BB), block 192. Thread t owns column c0+t.
__global__ __launch_bounds__(192)
void k_scatter3(const float* __restrict__ lh) {
    __shared__ int   sperm[SS];
    __shared__ float swv[SS];
    __shared__ int   ssoff[NN+1];
    int b  = blockIdx.y;
    int c0 = blockIdx.x * 192;
    int t  = threadIdx.x;
    for (int i = t; i < SS; i += 192) {
        sperm[i] = g_perm[b*SS + i];
        swv[i]   = g_wsort[b*SS + i];
    }
    for (int i = t; i < NN+1; i += 192) ssoff[i] = g_soff[b*(NN+1) + i];
    __syncthreads();
    const float* base = lh + ((size_t)b * SS) * HH + c0 + t;
    bf16* outp = g_nf + ((size_t)b * NN) * HH + c0 + t;
    for (int n = 0; n < NN; n++) {
        int i0 = ssoff[n], i1 = ssoff[n+1];
        float acc = 0.f;
        int i = i0;
        for (; i + 4 <= i1; i += 4) {
            float v0 = base[(size_t)sperm[i+0]*HH];
            float v1 = base[(size_t)sperm[i+1]*HH];
            float v2 = base[(size_t)sperm[i+2]*HH];
            float v3 = base[(size_t)sperm[i+3]*HH];
            acc += swv[i+0]*v0; acc += swv[i+1]*v1;
            acc += swv[i+2]*v2; acc += swv[i+3]*v3;
        }
        for (; i < i1; i++)
            acc += swv[i] * base[(size_t)sperm[i]*HH];
        outp[(size_t)n*HH] = __float2bfloat16(acc);
    }
}

// ---------------- K5: convert W1/W2 to transposed bf16 ----------------
__global__ void k_prepW(const float* __restrict__ W1, const float* __restrict__ W2) {
    int idx = blockIdx.x * blockDim.x + threadIdx.x;
    if (idx < HH*GHD) {
        int k = idx >> 7, n = idx & 127;
        g_W1t[n*HH + k] = __float2bfloat16(W1[idx]);
    } else {
        int i2 = idx - HH*GHD;
        if (i2 < GHD*GHD) {
            int k = i2 >> 7, n = i2 & 127;
            g_W2t[n*GHD + k] = __float2bfloat16(W2[i2]);
        }
    }
}

// ---------------- K7: dense normalized adjacency (bf16 out), 2 CTAs/batch --------
__global__ __launch_bounds__(256)
void k_adj(const int* __restrict__ ei) {
    __shared__ float sA[64*NN];          // 32KB
    __shared__ float sdeg[NN];
    __shared__ float sdinv[NN];
    int b = blockIdx.x >> 1;
    int half = blockIdx.x & 1;
    int lo = half * 64;
    int t = threadIdx.x;                 // 256 threads
    if (t < NN) sdeg[t] = 0.f;
    for (int i = t; i < 64*NN/4; i += 256)
        ((float4*)sA)[i] = make_float4(0.f,0.f,0.f,0.f);
    __syncthreads();
    const int* src = ei + (size_t)b * 2 * EE;
    const int* dst = src + EE;
    for (int e = t; e < EE; e += 256) atomicAdd(&sdeg[dst[e]], 1.f);
    __syncthreads();
    if (t < NN) sdinv[t] = rsqrtf(sdeg[t] + 1.f);
    __syncthreads();
    for (int e = t; e < EE; e += 256) {
        int s0 = src[e], d0 = dst[e];
        if ((d0 >> 6) == half)
            atomicAdd(&sA[(d0 - lo)*NN + s0], sdinv[s0] * sdinv[d0]);
    }
    if (t < 64) {
        int d = lo + t;
        atomicAdd(&sA[t*NN + d], sdinv[d] * sdinv[d]);
    }
    __syncthreads();
    bf16* Ab = g_A + (size_t)b * NN * NN + (size_t)lo * NN;
    for (int i = t; i < 64*NN/2; i += 256)
        ((__nv_bfloat162*)Ab)[i] = __floats2bfloat162_rn(sA[2*i], sA[2*i+1]);
}

// ---------------- K6/K9: Yt = (X @ Wt^T)^T, bf16 mma, transposed epilogue --------
// BM=64, BN=64, BK=32, 128 threads (4 warps 2m x 2n, warp 32x32). grid (M/64, 2).
// Tile loads: 64x32 bf16 = 2048 elems; each thread loads TWO uint4 (16 bf16). FIXED.
template<int KD, int SEL>
__global__ __launch_bounds__(128)
void k_gemm_tc() {
    const bf16* __restrict__ X  = SEL ? g_X1  : g_nf;
    const bf16* __restrict__ Wt = SEL ? g_W2t : g_W1t;
    bf16* __restrict__ Yt       = SEL ? g_H2t : g_H1t;
    __shared__ bf16 As[2][64][40];
    __shared__ bf16 Bs[2][64][40];
    int m0 = blockIdx.x * 64, n0 = blockIdx.y * 64;
    int t = threadIdx.x, lane = t & 31, warp = t >> 5;
    int gid = lane >> 2, tig = lane & 3;
    int wm = (warp >> 1) * 32, wn = (warp & 1) * 32;
    int aR = t >> 1, aH = (t & 1) * 16;   // thread covers cols [aH, aH+16)

    float acc[2][4][4];
#pragma unroll
    for (int i = 0; i < 2; i++)
#pragma unroll
        for (int j = 0; j < 4; j++)
#pragma unroll
            for (int q = 0; q < 4; q++) acc[i][j][q] = 0.f;

    const int NIT = KD / 32;
    uint4 pa0 = *(const uint4*)(X  + (size_t)(m0 + aR)*KD + aH);
    uint4 pa1 = *(const uint4*)(X  + (size_t)(m0 + aR)*KD + aH + 8);
    uint4 pb0 = *(const uint4*)(Wt + (size_t)(n0 + aR)*KD + aH);
    uint4 pb1 = *(const uint4*)(Wt + (size_t)(n0 + aR)*KD + aH + 8);
    *(uint4*)&As[0][aR][aH]     = pa0;
    *(uint4*)&As[0][aR][aH + 8] = pa1;
    *(uint4*)&Bs[0][aR][aH]     = pb0;
    *(uint4*)&Bs[0][aR][aH + 8] = pb1;

    for (int i = 0; i < NIT; i++) {
        __syncthreads();
        if (i + 1 < NIT) {
            int k0 = (i + 1) * 32;
            pa0 = *(const uint4*)(X  + (size_t)(m0 + aR)*KD + k0 + aH);
            pa1 = *(const uint4*)(X  + (size_t)(m0 + aR)*KD + k0 + aH + 8);
            pb0 = *(const uint4*)(Wt + (size_t)(n0 + aR)*KD + k0 + aH);
            pb1 = *(const uint4*)(Wt + (size_t)(n0 + aR)*KD + k0 + aH + 8);
        }
        mma_tile(As[i & 1], Bs[i & 1], acc, wm, wn, gid, tig);
        if (i + 1 < NIT) {
            int nx = (i + 1) & 1;
            *(uint4*)&As[nx][aR][aH]     = pa0;
            *(uint4*)&As[nx][aR][aH + 8] = pa1;
            *(uint4*)&Bs[nx][aR][aH]     = pb0;
            *(uint4*)&Bs[nx][aR][aH + 8] = pb1;
        }
    }

    // transposed epilogue through smem (reuse As storage): tile [64 m][68 n]
    __syncthreads();
    bf16* tp = &As[0][0][0];
#pragma unroll
    for (int i2 = 0; i2 < 2; i2++)
#pragma unroll
        for (int j = 0; j < 4; j++) {
            int r = wm + i2*16 + gid, cc = wn + j*8 + 2*tig;
            *(__nv_bfloat162*)&tp[r*68 + cc]     = __floats2bfloat162_rn(acc[i2][j][0], acc[i2][j][1]);
            *(__nv_bfloat162*)&tp[(r+8)*68 + cc] = __floats2bfloat162_rn(acc[i2][j][2], acc[i2][j][3]);
        }
    __syncthreads();
    int bb = m0 >> 7, nodeBase = m0 & 127;
    int rw = t >> 1, hf = (t & 1) * 32;
    bf16* outp = Yt + ((size_t)bb*GHD + n0 + rw) * NN + nodeBase + hf;
#pragma unroll
    for (int q = 0; q < 4; q++) {
        bf16 e[8];
#pragma unroll
        for (int k = 0; k < 8; k++) e[k] = tp[(hf + q*8 + k)*68 + rw];
        *(uint4*)&outp[q*8] = *(uint4*)e;
    }
}

// ---------------- K8/K10: relu(A_b @ H_b + bias) bf16 mma; POOL -> column mean ----
// grid (4 tiles, BB): tile = mt(0/1) | nt(0/1). 128 threads. Full tile loads. FIXED.
template<bool POOL>
__global__ __launch_bounds__(128)
void k_gcn_agg(const float* __restrict__ bias) {
    const bf16* __restrict__ Ht = POOL ? g_H2t : g_H1t;
    __shared__ bf16 As[2][64][40];
    __shared__ bf16 Bs[2][64][40];
    __shared__ float sred[64];
    int mt = blockIdx.x & 1, nt = blockIdx.x >> 1;
    int b = blockIdx.y;
    int t = threadIdx.x, lane = t & 31, warp = t >> 5;
    int gid = lane >> 2, tig = lane & 3;
    int wm = (warp >> 1) * 32, wn = (warp & 1) * 32;
    int aR = t >> 1, aH = (t & 1) * 16;

    if (POOL && t < 64) sred[t] = 0.f;

    const bf16* A = g_A + (size_t)b*NN*NN + (size_t)mt*64*NN;
    const bf16* B = Ht  + (size_t)b*GHD*NN + (size_t)nt*64*NN;

    float acc[2][4][4];
#pragma unroll
    for (int i = 0; i < 2; i++)
#pragma unroll
        for (int j = 0; j < 4; j++)
#pragma unroll
            for (int q = 0; q < 4; q++) acc[i][j][q] = 0.f;

    const int NIT = NN / 32;   // 4
    uint4 pa0 = *(const uint4*)(A + (size_t)aR*NN + aH);
    uint4 pa1 = *(const uint4*)(A + (size_t)aR*NN + aH + 8);
    uint4 pb0 = *(const uint4*)(B + (size_t)aR*NN + aH);
    uint4 pb1 = *(const uint4*)(B + (size_t)aR*NN + aH + 8);
    *(uint4*)&As[0][aR][aH]     = pa0;
    *(uint4*)&As[0][aR][aH + 8] = pa1;
    *(uint4*)&Bs[0][aR][aH]     = pb0;
    *(uint4*)&Bs[0][aR][aH + 8] = pb1;

    for (int i = 0; i < NIT; i++) {
        __syncthreads();
        if (i + 1 < NIT) {
            int k0 = (i + 1) * 32;
            pa0 = *(const uint4*)(A + (size_t)aR*NN + k0 + aH);
            pa1 = *(const uint4*)(A + (size_t)aR*NN + k0 + aH + 8);
            pb0 = *(const uint4*)(B + (size_t)aR*NN + k0 + aH);
            pb1 = *(const uint4*)(B + (size_t)aR*NN + k0 + aH + 8);
        }
        mma_tile(As[i & 1], Bs[i & 1], acc, wm, wn, gid, tig);
        if (i + 1 < NIT) {
            int nx = (i + 1) & 1;
            *(uint4*)&As[nx][aR][aH]     = pa0;
            *(uint4*)&As[nx][aR][aH + 8] = pa1;
            *(uint4*)&Bs[nx][aR][aH]     = pb0;
            *(uint4*)&Bs[nx][aR][aH + 8] = pb1;
        }
    }

    if (POOL) {
        float cs[4][2];
#pragma unroll
        for (int j = 0; j < 4; j++) { cs[j][0] = 0.f; cs[j][1] = 0.f; }
#pragma unroll
        for (int j = 0; j < 4; j++) {
            int cG = nt*64 + wn + j*8 + 2*tig;
            float b0 = bias[cG], b1 = bias[cG+1];
#pragma unroll
            for (int i2 = 0; i2 < 2; i2++) {
                cs[j][0] += fmaxf(acc[i2][j][0] + b0, 0.f) + fmaxf(acc[i2][j][2] + b0, 0.f);
                cs[j][1] += fmaxf(acc[i2][j][1] + b1, 0.f) + fmaxf(acc[i2][j][3] + b1, 0.f);
            }
        }
#pragma unroll
        for (int off = 4; off <= 16; off <<= 1)
#pragma unroll
            for (int j = 0; j < 4; j++) {
                cs[j][0] += __shfl_xor_sync(0xffffffffu, cs[j][0], off);
                cs[j][1] += __shfl_xor_sync(0xffffffffu, cs[j][1], off);
            }
        __syncthreads();   // sred init visible
        if (gid == 0) {
#pragma unroll
            for (int j = 0; j < 4; j++) {
                atomicAdd(&sred[wn + j*8 + 2*tig],     cs[j][0]);
                atomicAdd(&sred[wn + j*8 + 2*tig + 1], cs[j][1]);
            }
        }
        __syncthreads();
        if (t < 64)
            atomicAdd(&g_pooled[b*GHD + nt*64 + t], sred[t] * (1.f/128.f));
    } else {
#pragma unroll
        for (int i2 = 0; i2 < 2; i2++)
#pragma unroll
            for (int j = 0; j < 4; j++) {
                int rnode = mt*64 + wm + i2*16 + gid;
                int cG = nt*64 + wn + j*8 + 2*tig;
                float b0 = bias[cG], b1 = bias[cG+1];
                float v00 = fmaxf(acc[i2][j][0] + b0, 0.f);
                float v01 = fmaxf(acc[i2][j][1] + b1, 0.f);
                float v10 = fmaxf(acc[i2][j][2] + b0, 0.f);
                float v11 = fmaxf(acc[i2][j][3] + b1, 0.f);
                *(__nv_bfloat162*)&g_X1[((size_t)(b*NN + rnode))*GHD + cG]     = __floats2bfloat162_rn(v00, v01);
                *(__nv_bfloat162*)&g_X1[((size_t)(b*NN + rnode + 8))*GHD + cG] = __floats2bfloat162_rn(v10, v11);
            }
    }
}

// ---------------- K11: MLP head ----------------
__global__ __launch_bounds__(256)
void k_head(const float* __restrict__ lh, const float* __restrict__ Wf1,
            const float* __restrict__ bf1, const float* __restrict__ Wf2,
            const float* __restrict__ bf2, float* __restrict__ out) {
    __shared__ float xin[HH + GHD];
    __shared__ float sh[FHD];
    int b = blockIdx.x, t = threadIdx.x;   // 256
    for (int i = t; i < HH; i += 256) xin[i] = lh[((size_t)b*SS)*HH + i];
    if (t < GHD) xin[HH + t] = g_pooled[b*GHD + t];
    __syncthreads();
    float a0 = 0.f, a1 = 0.f, a2 = 0.f, a3 = 0.f;
    for (int k = 0; k < HH + GHD; k += 4) {
        a0 += xin[k+0] * Wf1[(k+0)*FHD + t];
        a1 += xin[k+1] * Wf1[(k+1)*FHD + t];
        a2 += xin[k+2] * Wf1[(k+2)*FHD + t];
        a3 += xin[k+3] * Wf1[(k+3)*FHD + t];
    }
    sh[t] = fmaxf(a0 + a1 + a2 + a3 + bf1[t], 0.f);
    __syncthreads();
    int w = t >> 5, lane = t & 31;
    if (w < 2) {
        float s = 0.f;
        for (int k = lane; k < FHD; k += 32) s += sh[k] * Wf2[k*2 + w];
#pragma unroll
        for (int o = 16; o; o >>= 1) s += __shfl_xor_sync(0xffffffffu, s, o);
        if (lane == 0) out[b*2 + w] = s + bf2[w];
    }
}

// ---------------- launch: ONLY kernel launches ----------------
extern "C" void kernel_launch(void* const* d_in, const int* in_sizes, int n_in,
                              void* d_out, int out_size) {
    const float* lh     = (const float*)d_in[0];
    const int*   submap = (const int*)  d_in[1];
    const int*   ei     = (const int*)  d_in[2];
    // d_in[3] = num_nodes (always 128, unused)
    const float* wr  = (const float*)d_in[4];
    const float* br  = (const float*)d_in[5];
    const float* W1  = (const float*)d_in[6];
    const float* b1  = (const float*)d_in[7];
    const float* W2  = (const float*)d_in[8];
    const float* b2  = (const float*)d_in[9];
    const float* Wf1 = (const float*)d_in[10];
    const float* bf1 = (const float*)d_in[11];
    const float* Wf2 = (const float*)d_in[12];
    const float* bf2 = (const float*)d_in[13];
    float* out = (float*)d_out;

    k_prep<<<BB, 128>>>(submap);                            // 1
    k_gate<<<(BB*SS)/8, 256>>>(lh, wr, br);                 // 2
    k_sort<<<BB, 128>>>(submap);                            // 3
    dim3 gsc(4, BB);
    k_scatter3<<<gsc, 192>>>(lh);                           // 4 <- profiled slot
    k_prepW<<<(HH*GHD + GHD*GHD + 255)/256, 256>>>(W1, W2); // 5
    dim3 gg1(BNN/64, 2);
    k_gemm_tc<HH, 0><<<gg1, 128>>>();                       // 6
    k_adj<<<2*BB, 256>>>(ei);                               // 7
    dim3 gag(4, BB);
    k_gcn_agg<false><<<gag, 128>>>(b1);                     // 8
    dim3 gg2(BNN/64, 2);
    k_gemm_tc<GHD, 1><<<gg2, 128>>>();                      // 9
    k_gcn_agg<true><<<gag, 128>>>(b2);                      // 10
    k_head<<<BB, 256>>>(lh, Wf1, bf1, Wf2, bf2, out);       // 11
}

// round 8
// speedup vs baseline: 1.5200x; 1.5200x over previous
#include <cuda_runtime.h>
#include <cuda_bf16.h>
#include <math.h>
#include <stdint.h>

// ---------------- problem constants ----------------
#define BB 64
#define SS 512
#define HH 768
#define NN 128
#define EE 1024
#define GHD 128
#define FHD 256
#define BNN (BB*NN)          // 8192

typedef __nv_bfloat16 bf16;

// ---------------- device scratch (no allocation allowed) ----------------
__device__ float g_gate[BB*SS];
__device__ int   g_cnt[BNN];
__device__ int   g_perm[BB*SS];
__device__ float g_wsort[BB*SS];          // gate * inv_cnt, sorted order
__device__ int   g_soff[BB*(NN+1)];
__device__ bf16  g_nf[BNN*HH];            // node features bf16, 12.6 MB
__device__ bf16  g_A[BB*NN*NN];           // normalized adjacency bf16
__device__ bf16  g_W1t[GHD*HH];           // W1 transposed [n][k] bf16
__device__ bf16  g_W2t[GHD*GHD];          // W2 transposed [n][k] bf16
__device__ bf16  g_H1t[BB*GHD*NN];        // H1 transposed per batch [feat][node]
__device__ bf16  g_X1[BNN*GHD];           // X1 normal [row][feat]
__device__ bf16  g_H2t[BB*GHD*NN];        // H2 transposed per batch
__device__ float g_pooled[BB*GHD];

// ---------------- bf16 mma m16n8k16 ----------------
__device__ __forceinline__ void mma_bf16(float* d, uint32_t a0, uint32_t a1,
                                         uint32_t a2, uint32_t a3,
                                         uint32_t b0, uint32_t b1) {
    asm volatile(
        "mma.sync.aligned.m16n8k16.row.col.f32.bf16.bf16.f32 "
        "{%0,%1,%2,%3}, {%4,%5,%6,%7}, {%8,%9}, {%0,%1,%2,%3};"
        : "+f"(d[0]), "+f"(d[1]), "+f"(d[2]), "+f"(d[3])
        : "r"(a0), "r"(a1), "r"(a2), "r"(a3), "r"(b0), "r"(b1));
}

// one BK=32 tile of MMA work; As/Bs are [64][40] bf16
__device__ __forceinline__ void mma_tile(const bf16 (*Ac)[40], const bf16 (*Bc)[40],
                                         float acc[2][4][4],
                                         int wm, int wn, int gid, int tig) {
#pragma unroll
    for (int kh = 0; kh < 32; kh += 16) {
        uint32_t a[2][4];
#pragma unroll
        for (int i2 = 0; i2 < 2; i2++) {
            int m = wm + i2*16;
            a[i2][0] = *(const uint32_t*)&Ac[m+gid  ][kh + 2*tig];
            a[i2][1] = *(const uint32_t*)&Ac[m+gid+8][kh + 2*tig];
            a[i2][2] = *(const uint32_t*)&Ac[m+gid  ][kh + 2*tig + 8];
            a[i2][3] = *(const uint32_t*)&Ac[m+gid+8][kh + 2*tig + 8];
        }
#pragma unroll
        for (int j = 0; j < 4; j++) {
            uint32_t b0 = *(const uint32_t*)&Bc[wn+j*8+gid][kh + 2*tig];
            uint32_t b1 = *(const uint32_t*)&Bc[wn+j*8+gid][kh + 2*tig + 8];
#pragma unroll
            for (int i2 = 0; i2 < 2; i2++)
                mma_bf16(acc[i2][j], a[i2][0], a[i2][1], a[i2][2], a[i2][3], b0, b1);
        }
    }
}

// ---------------- K1: token counts + zero pooled ----------------
__global__ void k_prep(const int* __restrict__ submap) {
    __shared__ int h[NN];
    int b = blockIdx.x, t = threadIdx.x;   // 128 threads
    if (t < NN) h[t] = 0;
    g_pooled[b*GHD + t] = 0.f;
    __syncthreads();
    for (int s = t; s < SS; s += blockDim.x)
        atomicAdd(&h[submap[b*SS + s]], 1);
    __syncthreads();
    if (t < NN) g_cnt[b*NN + t] = h[t];
}

// ---------------- K2: gate = sigmoid(lh . wr + br) ----------------
__global__ void k_gate(const float* __restrict__ lh, const float* __restrict__ wr,
                       const float* __restrict__ brp) {
    int warp = (blockIdx.x * blockDim.x + threadIdx.x) >> 5;
    int lane = threadIdx.x & 31;
    if (warp >= BB*SS) return;
    const float4* row = reinterpret_cast<const float4*>(lh + (size_t)warp * HH);
    const float4* w4  = reinterpret_cast<const float4*>(wr);
    float acc = 0.f;
#pragma unroll
    for (int i = 0; i < 6; i++) {
        float4 v = row[lane + i*32];
        float4 w = w4[lane + i*32];
        acc += v.x*w.x + v.y*w.y + v.z*w.z + v.w*w.w;
    }
#pragma unroll
    for (int o = 16; o; o >>= 1) acc += __shfl_xor_sync(0xffffffffu, acc, o);
    if (lane == 0) g_gate[warp] = 1.f / (1.f + __expf(-(acc + brp[0])));
}

// ---------------- K3: deterministic counting sort of tokens by node ----------------
__global__ __launch_bounds__(128)
void k_sort(const int* __restrict__ submap) {
    __shared__ int snode[SS];
    __shared__ int scnt[NN];
    __shared__ int soff[NN+1];
    int b = blockIdx.x, t = threadIdx.x;   // 128 threads
#pragma unroll
    for (int u = 0; u < 4; u++) snode[t + u*128] = submap[b*SS + t + u*128];
    scnt[t] = g_cnt[b*NN + t];
    __syncthreads();
    if (t == 0) {
        int run = 0;
        for (int n = 0; n < NN; n++) { soff[n] = run; run += scnt[n]; }
        soff[NN] = SS;
    }
    __syncthreads();
    {
        int o = soff[t];
        float inv = 1.f / (float)(scnt[t] < 1 ? 1 : scnt[t]);
        for (int s = 0; s < SS; s++) {
            if (snode[s] == t) {
                g_perm[b*SS + o]  = s;
                g_wsort[b*SS + o] = g_gate[b*SS + s] * inv;
                o++;
            }
        }
        g_soff[b*(NN+1) + t] = soff[t];
        if (t == 0) g_soff[b*(NN+1) + NN] = SS;
    }
}

// ---------------- K4 (PROFILED): sorted segment-mean, node-split grid ----------
// grid (3 H-chunks of 256, 8 node-groups of 16, BB). block 256, thread owns 1 col.
#define NGRP 8
#define NPG  (NN/NGRP)     // 16 nodes per group
__global__ __launch_bounds__(256)
void k_scatter4(const float* __restrict__ lh) {
    __shared__ int   sperm[SS];
    __shared__ float swv[SS];
    __shared__ int   ssoff[NPG + 1];
    int c0 = blockIdx.x * 256;
    int ng = blockIdx.y;
    int b  = blockIdx.z;
    int t  = threadIdx.x;
    int n0 = ng * NPG;
    // group token range (contiguous thanks to sort)
    if (t < NPG + 1) ssoff[t] = g_soff[b*(NN+1) + n0 + t];
    __syncthreads();
    int i0 = ssoff[0], i1 = ssoff[NPG];
    for (int i = i0 + t; i < i1; i += 256) {
        sperm[i - i0] = g_perm[b*SS + i];
        swv[i - i0]   = g_wsort[b*SS + i];
    }
    __syncthreads();
    const float* base = lh + ((size_t)b * SS) * HH + c0 + t;
    bf16* outp = g_nf + ((size_t)(b * NN + n0)) * HH + c0 + t;
#pragma unroll 1
    for (int n = 0; n < NPG; n++) {
        int j0 = ssoff[n] - i0, j1 = ssoff[n+1] - i0;
        float acc = 0.f;
        int i = j0;
        for (; i + 4 <= j1; i += 4) {
            float v0 = base[(size_t)sperm[i+0]*HH];
            float v1 = base[(size_t)sperm[i+1]*HH];
            float v2 = base[(size_t)sperm[i+2]*HH];
            float v3 = base[(size_t)sperm[i+3]*HH];
            acc += swv[i+0]*v0; acc += swv[i+1]*v1;
            acc += swv[i+2]*v2; acc += swv[i+3]*v3;
        }
        for (; i < j1; i++)
            acc += swv[i] * base[(size_t)sperm[i]*HH];
        outp[(size_t)n*HH] = __float2bfloat16(acc);
    }
}

// ---------------- K5: convert W1/W2 to transposed bf16 ----------------
__global__ void k_prepW(const float* __restrict__ W1, const float* __restrict__ W2) {
    int idx = blockIdx.x * blockDim.x + threadIdx.x;
    if (idx < HH*GHD) {
        int k = idx >> 7, n = idx & 127;
        g_W1t[n*HH + k] = __float2bfloat16(W1[idx]);
    } else {
        int i2 = idx - HH*GHD;
        if (i2 < GHD*GHD) {
            int k = i2 >> 7, n = i2 & 127;
            g_W2t[n*GHD + k] = __float2bfloat16(W2[i2]);
        }
    }
}

// ---------------- K7: dense normalized adjacency (bf16 out), 2 CTAs/batch --------
__global__ __launch_bounds__(256)
void k_adj(const int* __restrict__ ei) {
    __shared__ float sA[64*NN];          // 32KB
    __shared__ float sdeg[NN];
    __shared__ float sdinv[NN];
    int b = blockIdx.x >> 1;
    int half = blockIdx.x & 1;
    int lo = half * 64;
    int t = threadIdx.x;                 // 256 threads
    if (t < NN) sdeg[t] = 0.f;
    for (int i = t; i < 64*NN/4; i += 256)
        ((float4*)sA)[i] = make_float4(0.f,0.f,0.f,0.f);
    __syncthreads();
    const int* src = ei + (size_t)b * 2 * EE;
    const int* dst = src + EE;
    for (int e = t; e < EE; e += 256) atomicAdd(&sdeg[dst[e]], 1.f);
    __syncthreads();
    if (t < NN) sdinv[t] = rsqrtf(sdeg[t] + 1.f);
    __syncthreads();
    for (int e = t; e < EE; e += 256) {
        int s0 = src[e], d0 = dst[e];
        if ((d0 >> 6) == half)
            atomicAdd(&sA[(d0 - lo)*NN + s0], sdinv[s0] * sdinv[d0]);
    }
    if (t < 64) {
        int d = lo + t;
        atomicAdd(&sA[t*NN + d], sdinv[d] * sdinv[d]);
    }
    __syncthreads();
    bf16* Ab = g_A + (size_t)b * NN * NN + (size_t)lo * NN;
    for (int i = t; i < 64*NN/2; i += 256)
        ((__nv_bfloat162*)Ab)[i] = __floats2bfloat162_rn(sA[2*i], sA[2*i+1]);
}

// ---------------- K6/K9: Yt = (X @ Wt^T)^T, bf16 mma, transposed epilogue --------
template<int KD, int SEL>
__global__ __launch_bounds__(128)
void k_gemm_tc() {
    const bf16* __restrict__ X  = SEL ? g_X1  : g_nf;
    const bf16* __restrict__ Wt = SEL ? g_W2t : g_W1t;
    bf16* __restrict__ Yt       = SEL ? g_H2t : g_H1t;
    __shared__ bf16 As[2][64][40];
    __shared__ bf16 Bs[2][64][40];
    int m0 = blockIdx.x * 64, n0 = blockIdx.y * 64;
    int t = threadIdx.x, lane = t & 31, warp = t >> 5;
    int gid = lane >> 2, tig = lane & 3;
    int wm = (warp >> 1) * 32, wn = (warp & 1) * 32;
    int aR = t >> 1, aH = (t & 1) * 16;   // thread covers cols [aH, aH+16)

    float acc[2][4][4];
#pragma unroll
    for (int i = 0; i < 2; i++)
#pragma unroll
        for (int j = 0; j < 4; j++)
#pragma unroll
            for (int q = 0; q < 4; q++) acc[i][j][q] = 0.f;

    const int NIT = KD / 32;
    uint4 pa0 = *(const uint4*)(X  + (size_t)(m0 + aR)*KD + aH);
    uint4 pa1 = *(const uint4*)(X  + (size_t)(m0 + aR)*KD + aH + 8);
    uint4 pb0 = *(const uint4*)(Wt + (size_t)(n0 + aR)*KD + aH);
    uint4 pb1 = *(const uint4*)(Wt + (size_t)(n0 + aR)*KD + aH + 8);
    *(uint4*)&As[0][aR][aH]     = pa0;
    *(uint4*)&As[0][aR][aH + 8] = pa1;
    *(uint4*)&Bs[0][aR][aH]     = pb0;
    *(uint4*)&Bs[0][aR][aH + 8] = pb1;

    for (int i = 0; i < NIT; i++) {
        __syncthreads();
        if (i + 1 < NIT) {
            int k0 = (i + 1) * 32;
            pa0 = *(const uint4*)(X  + (size_t)(m0 + aR)*KD + k0 + aH);
            pa1 = *(const uint4*)(X  + (size_t)(m0 + aR)*KD + k0 + aH + 8);
            pb0 = *(const uint4*)(Wt + (size_t)(n0 + aR)*KD + k0 + aH);
            pb1 = *(const uint4*)(Wt + (size_t)(n0 + aR)*KD + k0 + aH + 8);
        }
        mma_tile(As[i & 1], Bs[i & 1], acc, wm, wn, gid, tig);
        if (i + 1 < NIT) {
            int nx = (i + 1) & 1;
            *(uint4*)&As[nx][aR][aH]     = pa0;
            *(uint4*)&As[nx][aR][aH + 8] = pa1;
            *(uint4*)&Bs[nx][aR][aH]     = pb0;
            *(uint4*)&Bs[nx][aR][aH + 8] = pb1;
        }
    }

    // transposed epilogue through smem (reuse As storage): tile [64 m][68 n]
    __syncthreads();
    bf16* tp = &As[0][0][0];
#pragma unroll
    for (int i2 = 0; i2 < 2; i2++)
#pragma unroll
        for (int j = 0; j < 4; j++) {
            int r = wm + i2*16 + gid, cc = wn + j*8 + 2*tig;
            *(__nv_bfloat162*)&tp[r*68 + cc]     = __floats2bfloat162_rn(acc[i2][j][0], acc[i2][j][1]);
            *(__nv_bfloat162*)&tp[(r+8)*68 + cc] = __floats2bfloat162_rn(acc[i2][j][2], acc[i2][j][3]);
        }
    __syncthreads();
    int bb = m0 >> 7, nodeBase = m0 & 127;
    int rw = t >> 1, hf = (t & 1) * 32;
    bf16* outp = Yt + ((size_t)bb*GHD + n0 + rw) * NN + nodeBase + hf;
#pragma unroll
    for (int q = 0; q < 4; q++) {
        bf16 e[8];
#pragma unroll
        for (int k = 0; k < 8; k++) e[k] = tp[(hf + q*8 + k)*68 + rw];
        *(uint4*)&outp[q*8] = *(uint4*)e;
    }
}

// ---------------- K8/K10: relu(A_b @ H_b + bias) bf16 mma; POOL -> column mean ----
template<bool POOL>
__global__ __launch_bounds__(128)
void k_gcn_agg(const float* __restrict__ bias) {
    const bf16* __restrict__ Ht = POOL ? g_H2t : g_H1t;
    __shared__ bf16 As[2][64][40];
    __shared__ bf16 Bs[2][64][40];
    __shared__ float sred[64];
    int mt = blockIdx.x & 1, nt = blockIdx.x >> 1;
    int b = blockIdx.y;
    int t = threadIdx.x, lane = t & 31, warp = t >> 5;
    int gid = lane >> 2, tig = lane & 3;
    int wm = (warp >> 1) * 32, wn = (warp & 1) * 32;
    int aR = t >> 1, aH = (t & 1) * 16;

    if (POOL && t < 64) sred[t] = 0.f;

    const bf16* A = g_A + (size_t)b*NN*NN + (size_t)mt*64*NN;
    const bf16* B = Ht  + (size_t)b*GHD*NN + (size_t)nt*64*NN;

    float acc[2][4][4];
#pragma unroll
    for (int i = 0; i < 2; i++)
#pragma unroll
        for (int j = 0; j < 4; j++)
#pragma unroll
            for (int q = 0; q < 4; q++) acc[i][j][q] = 0.f;

    const int NIT = NN / 32;   // 4
    uint4 pa0 = *(const uint4*)(A + (size_t)aR*NN + aH);
    uint4 pa1 = *(const uint4*)(A + (size_t)aR*NN + aH + 8);
    uint4 pb0 = *(const uint4*)(B + (size_t)aR*NN + aH);
    uint4 pb1 = *(const uint4*)(B + (size_t)aR*NN + aH + 8);
    *(uint4*)&As[0][aR][aH]     = pa0;
    *(uint4*)&As[0][aR][aH + 8] = pa1;
    *(uint4*)&Bs[0][aR][aH]     = pb0;
    *(uint4*)&Bs[0][aR][aH + 8] = pb1;

    for (int i = 0; i < NIT; i++) {
        __syncthreads();
        if (i + 1 < NIT) {
            int k0 = (i + 1) * 32;
            pa0 = *(const uint4*)(A + (size_t)aR*NN + k0 + aH);
            pa1 = *(const uint4*)(A + (size_t)aR*NN + k0 + aH + 8);
            pb0 = *(const uint4*)(B + (size_t)aR*NN + k0 + aH);
            pb1 = *(const uint4*)(B + (size_t)aR*NN + k0 + aH + 8);
        }
        mma_tile(As[i & 1], Bs[i & 1], acc, wm, wn, gid, tig);
        if (i + 1 < NIT) {
            int nx = (i + 1) & 1;
            *(uint4*)&As[nx][aR][aH]     = pa0;
            *(uint4*)&As[nx][aR][aH + 8] = pa1;
            *(uint4*)&Bs[nx][aR][aH]     = pb0;
            *(uint4*)&Bs[nx][aR][aH + 8] = pb1;
        }
    }

    if (POOL) {
        float cs[4][2];
#pragma unroll
        for (int j = 0; j < 4; j++) { cs[j][0] = 0.f; cs[j][1] = 0.f; }
#pragma unroll
        for (int j = 0; j < 4; j++) {
            int cG = nt*64 + wn + j*8 + 2*tig;
            float b0 = bias[cG], b1 = bias[cG+1];
#pragma unroll
            for (int i2 = 0; i2 < 2; i2++) {
                cs[j][0] += fmaxf(acc[i2][j][0] + b0, 0.f) + fmaxf(acc[i2][j][2] + b0, 0.f);
                cs[j][1] += fmaxf(acc[i2][j][1] + b1, 0.f) + fmaxf(acc[i2][j][3] + b1, 0.f);
            }
        }
#pragma unroll
        for (int off = 4; off <= 16; off <<= 1)
#pragma unroll
            for (int j = 0; j < 4; j++) {
                cs[j][0] += __shfl_xor_sync(0xffffffffu, cs[j][0], off);
                cs[j][1] += __shfl_xor_sync(0xffffffffu, cs[j][1], off);
            }
        __syncthreads();   // sred init visible
        if (gid == 0) {
#pragma unroll
            for (int j = 0; j < 4; j++) {
                atomicAdd(&sred[wn + j*8 + 2*tig],     cs[j][0]);
                atomicAdd(&sred[wn + j*8 + 2*tig + 1], cs[j][1]);
            }
        }
        __syncthreads();
        if (t < 64)
            atomicAdd(&g_pooled[b*GHD + nt*64 + t], sred[t] * (1.f/128.f));
    } else {
#pragma unroll
        for (int i2 = 0; i2 < 2; i2++)
#pragma unroll
            for (int j = 0; j < 4; j++) {
                int rnode = mt*64 + wm + i2*16 + gid;
                int cG = nt*64 + wn + j*8 + 2*tig;
                float b0 = bias[cG], b1 = bias[cG+1];
                float v00 = fmaxf(acc[i2][j][0] + b0, 0.f);
                float v01 = fmaxf(acc[i2][j][1] + b1, 0.f);
                float v10 = fmaxf(acc[i2][j][2] + b0, 0.f);
                float v11 = fmaxf(acc[i2][j][3] + b1, 0.f);
                *(__nv_bfloat162*)&g_X1[((size_t)(b*NN + rnode))*GHD + cG]     = __floats2bfloat162_rn(v00, v01);
                *(__nv_bfloat162*)&g_X1[((size_t)(b*NN + rnode + 8))*GHD + cG] = __floats2bfloat162_rn(v10, v11);
            }
    }
}

// ---------------- K11: MLP head ----------------
__global__ __launch_bounds__(256)
void k_head(const float* __restrict__ lh, const float* __restrict__ Wf1,
            const float* __restrict__ bf1, const float* __restrict__ Wf2,
            const float* __restrict__ bf2, float* __restrict__ out) {
    __shared__ float xin[HH + GHD];
    __shared__ float sh[FHD];
    int b = blockIdx.x, t = threadIdx.x;   // 256
    for (int i = t; i < HH; i += 256) xin[i] = lh[((size_t)b*SS)*HH + i];
    if (t < GHD) xin[HH + t] = g_pooled[b*GHD + t];
    __syncthreads();
    float a0 = 0.f, a1 = 0.f, a2 = 0.f, a3 = 0.f;
    for (int k = 0; k < HH + GHD; k += 4) {
        a0 += xin[k+0] * Wf1[(k+0)*FHD + t];
        a1 += xin[k+1] * Wf1[(k+1)*FHD + t];
        a2 += xin[k+2] * Wf1[(k+2)*FHD + t];
        a3 += xin[k+3] * Wf1[(k+3)*FHD + t];
    }
    sh[t] = fmaxf(a0 + a1 + a2 + a3 + bf1[t], 0.f);
    __syncthreads();
    int w = t >> 5, lane = t & 31;
    if (w < 2) {
        float s = 0.f;
        for (int k = lane; k < FHD; k += 32) s += sh[k] * Wf2[k*2 + w];
#pragma unroll
        for (int o = 16; o; o >>= 1) s += __shfl_xor_sync(0xffffffffu, s, o);
        if (lane == 0) out[b*2 + w] = s + bf2[w];
    }
}

// ---------------- launch: ONLY kernel launches ----------------
extern "C" void kernel_launch(void* const* d_in, const int* in_sizes, int n_in,
                              void* d_out, int out_size) {
    const float* lh     = (const float*)d_in[0];
    const int*   submap = (const int*)  d_in[1];
    const int*   ei     = (const int*)  d_in[2];
    // d_in[3] = num_nodes (always 128, unused)
    const float* wr  = (const float*)d_in[4];
    const float* br  = (const float*)d_in[5];
    const float* W1  = (const float*)d_in[6];
    const float* b1  = (const float*)d_in[7];
    const float* W2  = (const float*)d_in[8];
    const float* b2  = (const float*)d_in[9];
    const float* Wf1 = (const float*)d_in[10];
    const float* bf1 = (const float*)d_in[11];
    const float* Wf2 = (const float*)d_in[12];
    const float* bf2 = (const float*)d_in[13];
    float* out = (float*)d_out;

    k_prep<<<BB, 128>>>(submap);                            // 1
    k_gate<<<(BB*SS)/8, 256>>>(lh, wr, br);                 // 2
    k_sort<<<BB, 128>>>(submap);                            // 3
    dim3 gsc(HH/256, NGRP, BB);                             // (3, 8, 64) = 1536 CTAs
    k_scatter4<<<gsc, 256>>>(lh);                           // 4 <- profiled slot
    k_prepW<<<(HH*GHD + GHD*GHD + 255)/256, 256>>>(W1, W2); // 5
    dim3 gg1(BNN/64, 2);
    k_gemm_tc<HH, 0><<<gg1, 128>>>();                       // 6
    k_adj<<<2*BB, 256>>>(ei);                               // 7
    dim3 gag(4, BB);
    k_gcn_agg<false><<<gag, 128>>>(b1);                     // 8
    dim3 gg2(BNN/64, 2);
    k_gemm_tc<GHD, 1><<<gg2, 128>>>();                      // 9
    k_gcn_agg<true><<<gag, 128>>>(b2);                      // 10
    k_head<<<BB, 256>>>(lh, Wf1, bf1, Wf2, bf2, out);       // 11
}

// round 9
// speedup vs baseline: 1.7150x; 1.1283x over previous
#include <cuda_runtime.h>
#include <cuda_bf16.h>
#include <math.h>
#include <stdint.h>

// ---------------- problem constants ----------------
#define BB 64
#define SS 512
#define HH 768
#define NN 128
#define EE 1024
#define GHD 128
#define FHD 256
#define BNN (BB*NN)          // 8192

typedef __nv_bfloat16 bf16;

// ---------------- device scratch (no allocation allowed) ----------------
__device__ float g_gate[BB*SS];
__device__ int   g_cnt[BNN];
__device__ int   g_perm[BB*SS];
__device__ float g_wsort[BB*SS];          // gate * inv_cnt, sorted order
__device__ int   g_soff[BB*(NN+1)];
__device__ bf16  g_nf[BNN*HH];            // node features bf16, 12.6 MB
__device__ bf16  g_A[BB*NN*NN];           // normalized adjacency bf16
__device__ bf16  g_W1t[GHD*HH];           // W1 transposed [n][k] bf16
__device__ bf16  g_W2t[GHD*GHD];          // W2 transposed [n][k] bf16
__device__ bf16  g_H1t[BB*GHD*NN];        // H1 transposed per batch [feat][node]
__device__ bf16  g_X1[BNN*GHD];           // X1 normal [row][feat]
__device__ bf16  g_H2t[BB*GHD*NN];        // H2 transposed per batch
__device__ float g_pooled[BB*GHD];

// ---------------- bf16 mma m16n8k16 ----------------
__device__ __forceinline__ void mma_bf16(float* d, uint32_t a0, uint32_t a1,
                                         uint32_t a2, uint32_t a3,
                                         uint32_t b0, uint32_t b1) {
    asm volatile(
        "mma.sync.aligned.m16n8k16.row.col.f32.bf16.bf16.f32 "
        "{%0,%1,%2,%3}, {%4,%5,%6,%7}, {%8,%9}, {%0,%1,%2,%3};"
        : "+f"(d[0]), "+f"(d[1]), "+f"(d[2]), "+f"(d[3])
        : "r"(a0), "r"(a1), "r"(a2), "r"(a3), "r"(b0), "r"(b1));
}

// one BK=32 tile of MMA work; As/Bs are [64][40] bf16
__device__ __forceinline__ void mma_tile(const bf16 (*Ac)[40], const bf16 (*Bc)[40],
                                         float acc[2][4][4],
                                         int wm, int wn, int gid, int tig) {
#pragma unroll
    for (int kh = 0; kh < 32; kh += 16) {
        uint32_t a[2][4];
#pragma unroll
        for (int i2 = 0; i2 < 2; i2++) {
            int m = wm + i2*16;
            a[i2][0] = *(const uint32_t*)&Ac[m+gid  ][kh + 2*tig];
            a[i2][1] = *(const uint32_t*)&Ac[m+gid+8][kh + 2*tig];
            a[i2][2] = *(const uint32_t*)&Ac[m+gid  ][kh + 2*tig + 8];
            a[i2][3] = *(const uint32_t*)&Ac[m+gid+8][kh + 2*tig + 8];
        }
#pragma unroll
        for (int j = 0; j < 4; j++) {
            uint32_t b0 = *(const uint32_t*)&Bc[wn+j*8+gid][kh + 2*tig];
            uint32_t b1 = *(const uint32_t*)&Bc[wn+j*8+gid][kh + 2*tig + 8];
#pragma unroll
            for (int i2 = 0; i2 < 2; i2++)
                mma_bf16(acc[i2][j], a[i2][0], a[i2][1], a[i2][2], a[i2][3], b0, b1);
        }
    }
}

// ---------------- K1: token counts + zero pooled ----------------
__global__ void k_prep(const int* __restrict__ submap) {
    __shared__ int h[NN];
    int b = blockIdx.x, t = threadIdx.x;   // 128 threads
    if (t < NN) h[t] = 0;
    g_pooled[b*GHD + t] = 0.f;
    __syncthreads();
    for (int s = t; s < SS; s += blockDim.x)
        atomicAdd(&h[submap[b*SS + s]], 1);
    __syncthreads();
    if (t < NN) g_cnt[b*NN + t] = h[t];
}

// ---------------- K2: gate = sigmoid(lh . wr + br) ----------------
__global__ void k_gate(const float* __restrict__ lh, const float* __restrict__ wr,
                       const float* __restrict__ brp) {
    int warp = (blockIdx.x * blockDim.x + threadIdx.x) >> 5;
    int lane = threadIdx.x & 31;
    if (warp >= BB*SS) return;
    const float4* row = reinterpret_cast<const float4*>(lh + (size_t)warp * HH);
    const float4* w4  = reinterpret_cast<const float4*>(wr);
    float acc = 0.f;
#pragma unroll
    for (int i = 0; i < 6; i++) {
        float4 v = row[lane + i*32];
        float4 w = w4[lane + i*32];
        acc += v.x*w.x + v.y*w.y + v.z*w.z + v.w*w.w;
    }
#pragma unroll
    for (int o = 16; o; o >>= 1) acc += __shfl_xor_sync(0xffffffffu, acc, o);
    if (lane == 0) g_gate[warp] = 1.f / (1.f + __expf(-(acc + brp[0])));
}

// ---------------- K3: deterministic counting sort of tokens by node ----------------
__global__ __launch_bounds__(128)
void k_sort(const int* __restrict__ submap) {
    __shared__ int snode[SS];
    __shared__ int scnt[NN];
    __shared__ int soff[NN+1];
    int b = blockIdx.x, t = threadIdx.x;   // 128 threads
#pragma unroll
    for (int u = 0; u < 4; u++) snode[t + u*128] = submap[b*SS + t + u*128];
    scnt[t] = g_cnt[b*NN + t];
    __syncthreads();
    if (t == 0) {
        int run = 0;
        for (int n = 0; n < NN; n++) { soff[n] = run; run += scnt[n]; }
        soff[NN] = SS;
    }
    __syncthreads();
    {
        int o = soff[t];
        float inv = 1.f / (float)(scnt[t] < 1 ? 1 : scnt[t]);
        for (int s = 0; s < SS; s++) {
            if (snode[s] == t) {
                g_perm[b*SS + o]  = s;
                g_wsort[b*SS + o] = g_gate[b*SS + s] * inv;
                o++;
            }
        }
        g_soff[b*(NN+1) + t] = soff[t];
        if (t == 0) g_soff[b*(NN+1) + NN] = SS;
    }
}

// ---------------- K4 (PROFILED): sorted segment-mean, float4 per thread ----------
// grid (16 node-groups of 8, BB). block 192; thread t owns columns [4t, 4t+4).
#define NGRP 16
#define NPG  (NN/NGRP)     // 8 nodes per group
__global__ __launch_bounds__(192)
void k_scatter5(const float* __restrict__ lh) {
    __shared__ int   sperm[SS];
    __shared__ float swv[SS];
    __shared__ int   ssoff[NPG + 1];
    int ng = blockIdx.x;
    int b  = blockIdx.y;
    int t  = threadIdx.x;
    int n0 = ng * NPG;
    if (t < NPG + 1) ssoff[t] = g_soff[b*(NN+1) + n0 + t];
    __syncthreads();
    int i0 = ssoff[0], i1 = ssoff[NPG];
    for (int i = i0 + t; i < i1; i += 192) {
        sperm[i - i0] = g_perm[b*SS + i];
        swv[i - i0]   = g_wsort[b*SS + i];
    }
    __syncthreads();
    // row stride in float4 units = HH/4 = 192
    const float4* base = reinterpret_cast<const float4*>(lh + (size_t)b * SS * HH) + t;
    bf16* outp = g_nf + ((size_t)(b * NN + n0)) * HH + t*4;
#pragma unroll 1
    for (int n = 0; n < NPG; n++) {
        int j0 = ssoff[n] - i0, j1 = ssoff[n+1] - i0;
        float ax = 0.f, ay = 0.f, az = 0.f, aw = 0.f;
        int i = j0;
        for (; i + 4 <= j1; i += 4) {
            float4 v0 = base[(size_t)sperm[i+0] * 192];
            float4 v1 = base[(size_t)sperm[i+1] * 192];
            float4 v2 = base[(size_t)sperm[i+2] * 192];
            float4 v3 = base[(size_t)sperm[i+3] * 192];
            float w0 = swv[i+0], w1 = swv[i+1], w2 = swv[i+2], w3 = swv[i+3];
            ax += w0*v0.x; ay += w0*v0.y; az += w0*v0.z; aw += w0*v0.w;
            ax += w1*v1.x; ay += w1*v1.y; az += w1*v1.z; aw += w1*v1.w;
            ax += w2*v2.x; ay += w2*v2.y; az += w2*v2.z; aw += w2*v2.w;
            ax += w3*v3.x; ay += w3*v3.y; az += w3*v3.z; aw += w3*v3.w;
        }
        for (; i < j1; i++) {
            float4 v = base[(size_t)sperm[i] * 192];
            float w = swv[i];
            ax += w*v.x; ay += w*v.y; az += w*v.z; aw += w*v.w;
        }
        __nv_bfloat162 o0 = __floats2bfloat162_rn(ax, ay);
        __nv_bfloat162 o1 = __floats2bfloat162_rn(az, aw);
        *(__nv_bfloat162*)(outp + (size_t)n*HH)     = o0;
        *(__nv_bfloat162*)(outp + (size_t)n*HH + 2) = o1;
    }
}

// ---------------- K5: convert W1/W2 to transposed bf16 ----------------
__global__ void k_prepW(const float* __restrict__ W1, const float* __restrict__ W2) {
    int idx = blockIdx.x * blockDim.x + threadIdx.x;
    if (idx < HH*GHD) {
        int k = idx >> 7, n = idx & 127;
        g_W1t[n*HH + k] = __float2bfloat16(W1[idx]);
    } else {
        int i2 = idx - HH*GHD;
        if (i2 < GHD*GHD) {
            int k = i2 >> 7, n = i2 & 127;
            g_W2t[n*GHD + k] = __float2bfloat16(W2[i2]);
        }
    }
}

// ---------------- K7: dense normalized adjacency (bf16 out), 2 CTAs/batch --------
__global__ __launch_bounds__(256)
void k_adj(const int* __restrict__ ei) {
    __shared__ float sA[64*NN];          // 32KB
    __shared__ float sdeg[NN];
    __shared__ float sdinv[NN];
    int b = blockIdx.x >> 1;
    int half = blockIdx.x & 1;
    int lo = half * 64;
    int t = threadIdx.x;                 // 256 threads
    if (t < NN) sdeg[t] = 0.f;
    for (int i = t; i < 64*NN/4; i += 256)
        ((float4*)sA)[i] = make_float4(0.f,0.f,0.f,0.f);
    __syncthreads();
    const int* src = ei + (size_t)b * 2 * EE;
    const int* dst = src + EE;
    for (int e = t; e < EE; e += 256) atomicAdd(&sdeg[dst[e]], 1.f);
    __syncthreads();
    if (t < NN) sdinv[t] = rsqrtf(sdeg[t] + 1.f);
    __syncthreads();
    for (int e = t; e < EE; e += 256) {
        int s0 = src[e], d0 = dst[e];
        if ((d0 >> 6) == half)
            atomicAdd(&sA[(d0 - lo)*NN + s0], sdinv[s0] * sdinv[d0]);
    }
    if (t < 64) {
        int d = lo + t;
        atomicAdd(&sA[t*NN + d], sdinv[d] * sdinv[d]);
    }
    __syncthreads();
    bf16* Ab = g_A + (size_t)b * NN * NN + (size_t)lo * NN;
    for (int i = t; i < 64*NN/2; i += 256)
        ((__nv_bfloat162*)Ab)[i] = __floats2bfloat162_rn(sA[2*i], sA[2*i+1]);
}

// ---------------- K6/K9: Yt = (X @ Wt^T)^T, bf16 mma, transposed epilogue --------
template<int KD, int SEL>
__global__ __launch_bounds__(128)
void k_gemm_tc() {
    const bf16* __restrict__ X  = SEL ? g_X1  : g_nf;
    const bf16* __restrict__ Wt = SEL ? g_W2t : g_W1t;
    bf16* __restrict__ Yt       = SEL ? g_H2t : g_H1t;
    __shared__ bf16 As[2][64][40];
    __shared__ bf16 Bs[2][64][40];
    int m0 = blockIdx.x * 64, n0 = blockIdx.y * 64;
    int t = threadIdx.x, lane = t & 31, warp = t >> 5;
    int gid = lane >> 2, tig = lane & 3;
    int wm = (warp >> 1) * 32, wn = (warp & 1) * 32;
    int aR = t >> 1, aH = (t & 1) * 16;   // thread covers cols [aH, aH+16)

    float acc[2][4][4];
#pragma unroll
    for (int i = 0; i < 2; i++)
#pragma unroll
        for (int j = 0; j < 4; j++)
#pragma unroll
            for (int q = 0; q < 4; q++) acc[i][j][q] = 0.f;

    const int NIT = KD / 32;
    uint4 pa0 = *(const uint4*)(X  + (size_t)(m0 + aR)*KD + aH);
    uint4 pa1 = *(const uint4*)(X  + (size_t)(m0 + aR)*KD + aH + 8);
    uint4 pb0 = *(const uint4*)(Wt + (size_t)(n0 + aR)*KD + aH);
    uint4 pb1 = *(const uint4*)(Wt + (size_t)(n0 + aR)*KD + aH + 8);
    *(uint4*)&As[0][aR][aH]     = pa0;
    *(uint4*)&As[0][aR][aH + 8] = pa1;
    *(uint4*)&Bs[0][aR][aH]     = pb0;
    *(uint4*)&Bs[0][aR][aH + 8] = pb1;

    for (int i = 0; i < NIT; i++) {
        __syncthreads();
        if (i + 1 < NIT) {
            int k0 = (i + 1) * 32;
            pa0 = *(const uint4*)(X  + (size_t)(m0 + aR)*KD + k0 + aH);
            pa1 = *(const uint4*)(X  + (size_t)(m0 + aR)*KD + k0 + aH + 8);
            pb0 = *(const uint4*)(Wt + (size_t)(n0 + aR)*KD + k0 + aH);
            pb1 = *(const uint4*)(Wt + (size_t)(n0 + aR)*KD + k0 + aH + 8);
        }
        mma_tile(As[i & 1], Bs[i & 1], acc, wm, wn, gid, tig);
        if (i + 1 < NIT) {
            int nx = (i + 1) & 1;
            *(uint4*)&As[nx][aR][aH]     = pa0;
            *(uint4*)&As[nx][aR][aH + 8] = pa1;
            *(uint4*)&Bs[nx][aR][aH]     = pb0;
            *(uint4*)&Bs[nx][aR][aH + 8] = pb1;
        }
    }

    // transposed epilogue through smem (reuse As storage): tile [64 m][68 n]
    __syncthreads();
    bf16* tp = &As[0][0][0];
#pragma unroll
    for (int i2 = 0; i2 < 2; i2++)
#pragma unroll
        for (int j = 0; j < 4; j++) {
            int r = wm + i2*16 + gid, cc = wn + j*8 + 2*tig;
            *(__nv_bfloat162*)&tp[r*68 + cc]     = __floats2bfloat162_rn(acc[i2][j][0], acc[i2][j][1]);
            *(__nv_bfloat162*)&tp[(r+8)*68 + cc] = __floats2bfloat162_rn(acc[i2][j][2], acc[i2][j][3]);
        }
    __syncthreads();
    int bb = m0 >> 7, nodeBase = m0 & 127;
    int rw = t >> 1, hf = (t & 1) * 32;
    bf16* outp = Yt + ((size_t)bb*GHD + n0 + rw) * NN + nodeBase + hf;
#pragma unroll
    for (int q = 0; q < 4; q++) {
        bf16 e[8];
#pragma unroll
        for (int k = 0; k < 8; k++) e[k] = tp[(hf + q*8 + k)*68 + rw];
        *(uint4*)&outp[q*8] = *(uint4*)e;
    }
}

// ---------------- K8/K10: relu(A_b @ H_b + bias) bf16 mma; POOL -> column mean ----
template<bool POOL>
__global__ __launch_bounds__(128)
void k_gcn_agg(const float* __restrict__ bias) {
    const bf16* __restrict__ Ht = POOL ? g_H2t : g_H1t;
    __shared__ bf16 As[2][64][40];
    __shared__ bf16 Bs[2][64][40];
    __shared__ float sred[64];
    int mt = blockIdx.x & 1, nt = blockIdx.x >> 1;
    int b = blockIdx.y;
    int t = threadIdx.x, lane = t & 31, warp = t >> 5;
    int gid = lane >> 2, tig = lane & 3;
    int wm = (warp >> 1) * 32, wn = (warp & 1) * 32;
    int aR = t >> 1, aH = (t & 1) * 16;

    if (POOL && t < 64) sred[t] = 0.f;

    const bf16* A = g_A + (size_t)b*NN*NN + (size_t)mt*64*NN;
    const bf16* B = Ht  + (size_t)b*GHD*NN + (size_t)nt*64*NN;

    float acc[2][4][4];
#pragma unroll
    for (int i = 0; i < 2; i++)
#pragma unroll
        for (int j = 0; j < 4; j++)
#pragma unroll
            for (int q = 0; q < 4; q++) acc[i][j][q] = 0.f;

    const int NIT = NN / 32;   // 4
    uint4 pa0 = *(const uint4*)(A + (size_t)aR*NN + aH);
    uint4 pa1 = *(const uint4*)(A + (size_t)aR*NN + aH + 8);
    uint4 pb0 = *(const uint4*)(B + (size_t)aR*NN + aH);
    uint4 pb1 = *(const uint4*)(B + (size_t)aR*NN + aH + 8);
    *(uint4*)&As[0][aR][aH]     = pa0;
    *(uint4*)&As[0][aR][aH + 8] = pa1;
    *(uint4*)&Bs[0][aR][aH]     = pb0;
    *(uint4*)&Bs[0][aR][aH + 8] = pb1;

    for (int i = 0; i < NIT; i++) {
        __syncthreads();
        if (i + 1 < NIT) {
            int k0 = (i + 1) * 32;
            pa0 = *(const uint4*)(A + (size_t)aR*NN + k0 + aH);
            pa1 = *(const uint4*)(A + (size_t)aR*NN + k0 + aH + 8);
            pb0 = *(const uint4*)(B + (size_t)aR*NN + k0 + aH);
            pb1 = *(const uint4*)(B + (size_t)aR*NN + k0 + aH + 8);
        }
        mma_tile(As[i & 1], Bs[i & 1], acc, wm, wn, gid, tig);
        if (i + 1 < NIT) {
            int nx = (i + 1) & 1;
            *(uint4*)&As[nx][aR][aH]     = pa0;
            *(uint4*)&As[nx][aR][aH + 8] = pa1;
            *(uint4*)&Bs[nx][aR][aH]     = pb0;
            *(uint4*)&Bs[nx][aR][aH + 8] = pb1;
        }
    }

    if (POOL) {
        float cs[4][2];
#pragma unroll
        for (int j = 0; j < 4; j++) { cs[j][0] = 0.f; cs[j][1] = 0.f; }
#pragma unroll
        for (int j = 0; j < 4; j++) {
            int cG = nt*64 + wn + j*8 + 2*tig;
            float b0 = bias[cG], b1 = bias[cG+1];
#pragma unroll
            for (int i2 = 0; i2 < 2; i2++) {
                cs[j][0] += fmaxf(acc[i2][j][0] + b0, 0.f) + fmaxf(acc[i2][j][2] + b0, 0.f);
                cs[j][1] += fmaxf(acc[i2][j][1] + b1, 0.f) + fmaxf(acc[i2][j][3] + b1, 0.f);
            }
        }
#pragma unroll
        for (int off = 4; off <= 16; off <<= 1)
#pragma unroll
            for (int j = 0; j < 4; j++) {
                cs[j][0] += __shfl_xor_sync(0xffffffffu, cs[j][0], off);
                cs[j][1] += __shfl_xor_sync(0xffffffffu, cs[j][1], off);
            }
        __syncthreads();   // sred init visible
        if (gid == 0) {
#pragma unroll
            for (int j = 0; j < 4; j++) {
                atomicAdd(&sred[wn + j*8 + 2*tig],     cs[j][0]);
                atomicAdd(&sred[wn + j*8 + 2*tig + 1], cs[j][1]);
            }
        }
        __syncthreads();
        if (t < 64)
            atomicAdd(&g_pooled[b*GHD + nt*64 + t], sred[t] * (1.f/128.f));
    } else {
#pragma unroll
        for (int i2 = 0; i2 < 2; i2++)
#pragma unroll
            for (int j = 0; j < 4; j++) {
                int rnode = mt*64 + wm + i2*16 + gid;
                int cG = nt*64 + wn + j*8 + 2*tig;
                float b0 = bias[cG], b1 = bias[cG+1];
                float v00 = fmaxf(acc[i2][j][0] + b0, 0.f);
                float v01 = fmaxf(acc[i2][j][1] + b1, 0.f);
                float v10 = fmaxf(acc[i2][j][2] + b0, 0.f);
                float v11 = fmaxf(acc[i2][j][3] + b1, 0.f);
                *(__nv_bfloat162*)&g_X1[((size_t)(b*NN + rnode))*GHD + cG]     = __floats2bfloat162_rn(v00, v01);
                *(__nv_bfloat162*)&g_X1[((size_t)(b*NN + rnode + 8))*GHD + cG] = __floats2bfloat162_rn(v10, v11);
            }
    }
}

// ---------------- K11: MLP head ----------------
__global__ __launch_bounds__(256)
void k_head(const float* __restrict__ lh, const float* __restrict__ Wf1,
            const float* __restrict__ bf1, const float* __restrict__ Wf2,
            const float* __restrict__ bf2, float* __restrict__ out) {
    __shared__ float xin[HH + GHD];
    __shared__ float sh[FHD];
    int b = blockIdx.x, t = threadIdx.x;   // 256
    for (int i = t; i < HH; i += 256) xin[i] = lh[((size_t)b*SS)*HH + i];
    if (t < GHD) xin[HH + t] = g_pooled[b*GHD + t];
    __syncthreads();
    float a0 = 0.f, a1 = 0.f, a2 = 0.f, a3 = 0.f;
    for (int k = 0; k < HH + GHD; k += 4) {
        a0 += xin[k+0] * Wf1[(k+0)*FHD + t];
        a1 += xin[k+1] * Wf1[(k+1)*FHD + t];
        a2 += xin[k+2] * Wf1[(k+2)*FHD + t];
        a3 += xin[k+3] * Wf1[(k+3)*FHD + t];
    }
    sh[t] = fmaxf(a0 + a1 + a2 + a3 + bf1[t], 0.f);
    __syncthreads();
    int w = t >> 5, lane = t & 31;
    if (w < 2) {
        float s = 0.f;
        for (int k = lane; k < FHD; k += 32) s += sh[k] * Wf2[k*2 + w];
#pragma unroll
        for (int o = 16; o; o >>= 1) s += __shfl_xor_sync(0xffffffffu, s, o);
        if (lane == 0) out[b*2 + w] = s + bf2[w];
    }
}

// ---------------- launch: ONLY kernel launches ----------------
extern "C" void kernel_launch(void* const* d_in, const int* in_sizes, int n_in,
                              void* d_out, int out_size) {
    const float* lh     = (const float*)d_in[0];
    const int*   submap = (const int*)  d_in[1];
    const int*   ei     = (const int*)  d_in[2];
    // d_in[3] = num_nodes (always 128, unused)
    const float* wr  = (const float*)d_in[4];
    const float* br  = (const float*)d_in[5];
    const float* W1  = (const float*)d_in[6];
    const float* b1  = (const float*)d_in[7];
    const float* W2  = (const float*)d_in[8];
    const float* b2  = (const float*)d_in[9];
    const float* Wf1 = (const float*)d_in[10];
    const float* bf1 = (const float*)d_in[11];
    const float* Wf2 = (const float*)d_in[12];
    const float* bf2 = (const float*)d_in[13];
    float* out = (float*)d_out;

    k_prep<<<BB, 128>>>(submap);                            // 1
    k_gate<<<(BB*SS)/8, 256>>>(lh, wr, br);                 // 2
    k_sort<<<BB, 128>>>(submap);                            // 3
    dim3 gsc(NGRP, BB);                                     // (16, 64) = 1024 CTAs
    k_scatter5<<<gsc, 192>>>(lh);                           // 4 <- profiled slot
    k_prepW<<<(HH*GHD + GHD*GHD + 255)/256, 256>>>(W1, W2); // 5
    dim3 gg1(BNN/64, 2);
    k_gemm_tc<HH, 0><<<gg1, 128>>>();                       // 6
    k_adj<<<2*BB, 256>>>(ei);                               // 7
    dim3 gag(4, BB);
    k_gcn_agg<false><<<gag, 128>>>(b1);                     // 8
    dim3 gg2(BNN/64, 2);
    k_gemm_tc<GHD, 1><<<gg2, 128>>>();                      // 9
    k_gcn_agg<true><<<gag, 128>>>(b2);                      // 10
    k_head<<<BB, 256>>>(lh, Wf1, bf1, Wf2, bf2, out);       // 11
}

// round 10
// speedup vs baseline: 1.9507x; 1.1374x over previous
#include <cuda_runtime.h>
#include <cuda_bf16.h>
#include <math.h>
#include <stdint.h>

// ---------------- problem constants ----------------
#define BB 64
#define SS 512
#define HH 768
#define NN 128
#define EE 1024
#define GHD 128
#define FHD 256
#define BNN (BB*NN)          // 8192

typedef __nv_bfloat16 bf16;

// ---------------- device scratch (no allocation allowed) ----------------
__device__ int   g_perm[BB*SS];
__device__ int   g_soff[BB*(NN+1)];
__device__ bf16  g_nf[BNN*HH];            // node features bf16, 12.6 MB
__device__ bf16  g_A[BB*NN*NN];           // normalized adjacency bf16
__device__ bf16  g_W1t[GHD*HH];           // W1 transposed [n][k] bf16
__device__ bf16  g_W2t[GHD*GHD];          // W2 transposed [n][k] bf16
__device__ bf16  g_H1t[BB*GHD*NN];        // H1 transposed per batch [feat][node]
__device__ bf16  g_X1[BNN*GHD];           // X1 normal [row][feat]
__device__ bf16  g_H2t[BB*GHD*NN];        // H2 transposed per batch
__device__ float g_pooled[BB*GHD];

// ---------------- bf16 mma m16n8k16 ----------------
__device__ __forceinline__ void mma_bf16(float* d, uint32_t a0, uint32_t a1,
                                         uint32_t a2, uint32_t a3,
                                         uint32_t b0, uint32_t b1) {
    asm volatile(
        "mma.sync.aligned.m16n8k16.row.col.f32.bf16.bf16.f32 "
        "{%0,%1,%2,%3}, {%4,%5,%6,%7}, {%8,%9}, {%0,%1,%2,%3};"
        : "+f"(d[0]), "+f"(d[1]), "+f"(d[2]), "+f"(d[3])
        : "r"(a0), "r"(a1), "r"(a2), "r"(a3), "r"(b0), "r"(b1));
}

// one BK=32 tile of MMA work; As/Bs are [64][40] bf16
__device__ __forceinline__ void mma_tile(const bf16 (*Ac)[40], const bf16 (*Bc)[40],
                                         float acc[2][4][4],
                                         int wm, int wn, int gid, int tig) {
#pragma unroll
    for (int kh = 0; kh < 32; kh += 16) {
        uint32_t a[2][4];
#pragma unroll
        for (int i2 = 0; i2 < 2; i2++) {
            int m = wm + i2*16;
            a[i2][0] = *(const uint32_t*)&Ac[m+gid  ][kh + 2*tig];
            a[i2][1] = *(const uint32_t*)&Ac[m+gid+8][kh + 2*tig];
            a[i2][2] = *(const uint32_t*)&Ac[m+gid  ][kh + 2*tig + 8];
            a[i2][3] = *(const uint32_t*)&Ac[m+gid+8][kh + 2*tig + 8];
        }
#pragma unroll
        for (int j = 0; j < 4; j++) {
            uint32_t b0 = *(const uint32_t*)&Bc[wn+j*8+gid][kh + 2*tig];
            uint32_t b1 = *(const uint32_t*)&Bc[wn+j*8+gid][kh + 2*tig + 8];
#pragma unroll
            for (int i2 = 0; i2 < 2; i2++)
                mma_bf16(acc[i2][j], a[i2][0], a[i2][1], a[i2][2], a[i2][3], b0, b1);
        }
    }
}

// ---------------- K1: counts + deterministic counting sort of tokens by node ------
__global__ __launch_bounds__(128)
void k_sortc(const int* __restrict__ submap) {
    __shared__ int snode[SS];
    __shared__ int scnt[NN];
    __shared__ int soff[NN+1];
    int b = blockIdx.x, t = threadIdx.x;   // 128 threads
#pragma unroll
    for (int u = 0; u < 4; u++) snode[t + u*128] = submap[b*SS + t + u*128];
    scnt[t] = 0;
    __syncthreads();
#pragma unroll
    for (int u = 0; u < 4; u++) atomicAdd(&scnt[snode[t + u*128]], 1);
    __syncthreads();
    if (t == 0) {
        int run = 0;
        for (int n = 0; n < NN; n++) { soff[n] = run; run += scnt[n]; }
        soff[NN] = SS;
    }
    __syncthreads();
    {
        int o = soff[t];
        for (int s = 0; s < SS; s++)
            if (snode[s] == t) g_perm[b*SS + o++] = s;
        g_soff[b*(NN+1) + t] = soff[t];
        if (t == 0) g_soff[b*(NN+1) + NN] = SS;
    }
}

// ---------------- K2: convert W1/W2 to transposed bf16 + zero pooled -------------
__global__ void k_prepWz(const float* __restrict__ W1, const float* __restrict__ W2) {
    int idx = blockIdx.x * blockDim.x + threadIdx.x;
    if (idx < HH*GHD) {
        int k = idx >> 7, n = idx & 127;
        g_W1t[n*HH + k] = __float2bfloat16(W1[idx]);
    } else if (idx < HH*GHD + GHD*GHD) {
        int i2 = idx - HH*GHD;
        int k = i2 >> 7, n = i2 & 127;
        g_W2t[n*GHD + k] = __float2bfloat16(W2[i2]);
    } else {
        int i3 = idx - HH*GHD - GHD*GHD;
        if (i3 < BB*GHD) g_pooled[i3] = 0.f;
    }
}

// ---------------- K3: FUSED gate + sorted segment-mean -----------------------
// grid (16 node-groups of 8, BB). block 192; thread t owns columns [4t, 4t+4).
// Phase A: 6 warps compute gate[i] = sigmoid(lh[row].wr + br) (full-row reads).
// Phase B: accumulate gate-weighted rows (L2 hits), scale by 1/cnt at end.
#define NGRP 16
#define NPG  (NN/NGRP)     // 8 nodes per group
__global__ __launch_bounds__(192)
void k_scatter6(const float* __restrict__ lh, const float* __restrict__ wr,
                const float* __restrict__ brp) {
    __shared__ int    sperm[SS];
    __shared__ float  sg[SS];
    __shared__ int    ssoff[NPG + 1];
    __shared__ float4 swr[HH/4];         // 192 float4 = wr
    int ng = blockIdx.x;
    int b  = blockIdx.y;
    int t  = threadIdx.x;
    if (t < NPG + 1) ssoff[t] = g_soff[b*(NN+1) + ng*NPG + t];
    swr[t] = ((const float4*)wr)[t];     // exactly 192 threads
    __syncthreads();
    int i0 = ssoff[0], i1 = ssoff[NPG];
    for (int i = i0 + t; i < i1; i += 192)
        sperm[i - i0] = g_perm[b*SS + i];
    __syncthreads();

    const float4* lb = reinterpret_cast<const float4*>(lh + (size_t)b * SS * HH);
    float brv = __ldg(brp);
    int w = t >> 5, lane = t & 31;
    // Phase A: gates (one token per warp, round-robin)
    for (int i = i0 + w; i < i1; i += 6) {
        const float4* row = lb + (size_t)sperm[i - i0] * 192;
        float d = 0.f;
#pragma unroll
        for (int q = 0; q < 6; q++) {
            float4 v  = row[lane + q*32];
            float4 wv = swr[lane + q*32];
            d += v.x*wv.x + v.y*wv.y + v.z*wv.z + v.w*wv.w;
        }
#pragma unroll
        for (int o = 16; o; o >>= 1) d += __shfl_xor_sync(0xffffffffu, d, o);
        if (lane == 0) sg[i - i0] = 1.f / (1.f + __expf(-(d + brv)));
    }
    __syncthreads();

    // Phase B: weighted accumulate per node (rows L2-resident from phase A)
    const float4* base = lb + t;
    bf16* outp = g_nf + ((size_t)(b * NN + ng * NPG)) * HH + t*4;
#pragma unroll 1
    for (int n = 0; n < NPG; n++) {
        int j0 = ssoff[n] - i0, j1 = ssoff[n+1] - i0;
        int cnt = j1 - j0;
        float inv = 1.f / (float)(cnt < 1 ? 1 : cnt);
        float ax = 0.f, ay = 0.f, az = 0.f, aw = 0.f;
        int i = j0;
        for (; i + 4 <= j1; i += 4) {
            float4 v0 = base[(size_t)sperm[i+0] * 192];
            float4 v1 = base[(size_t)sperm[i+1] * 192];
            float4 v2 = base[(size_t)sperm[i+2] * 192];
            float4 v3 = base[(size_t)sperm[i+3] * 192];
            float w0 = sg[i+0], w1 = sg[i+1], w2 = sg[i+2], w3 = sg[i+3];
            ax += w0*v0.x; ay += w0*v0.y; az += w0*v0.z; aw += w0*v0.w;
            ax += w1*v1.x; ay += w1*v1.y; az += w1*v1.z; aw += w1*v1.w;
            ax += w2*v2.x; ay += w2*v2.y; az += w2*v2.z; aw += w2*v2.w;
            ax += w3*v3.x; ay += w3*v3.y; az += w3*v3.z; aw += w3*v3.w;
        }
        for (; i < j1; i++) {
            float4 v = base[(size_t)sperm[i] * 192];
            float ww = sg[i];
            ax += ww*v.x; ay += ww*v.y; az += ww*v.z; aw += ww*v.w;
        }
        __nv_bfloat162 o0 = __floats2bfloat162_rn(ax*inv, ay*inv);
        __nv_bfloat162 o1 = __floats2bfloat162_rn(az*inv, aw*inv);
        *(__nv_bfloat162*)(outp + (size_t)n*HH)     = o0;
        *(__nv_bfloat162*)(outp + (size_t)n*HH + 2) = o1;
    }
}

// ---------------- K5: dense normalized adjacency (bf16 out), 2 CTAs/batch --------
__global__ __launch_bounds__(256)
void k_adj(const int* __restrict__ ei) {
    __shared__ float sA[64*NN];          // 32KB
    __shared__ float sdeg[NN];
    __shared__ float sdinv[NN];
    int b = blockIdx.x >> 1;
    int half = blockIdx.x & 1;
    int lo = half * 64;
    int t = threadIdx.x;                 // 256 threads
    if (t < NN) sdeg[t] = 0.f;
    for (int i = t; i < 64*NN/4; i += 256)
        ((float4*)sA)[i] = make_float4(0.f,0.f,0.f,0.f);
    __syncthreads();
    const int* src = ei + (size_t)b * 2 * EE;
    const int* dst = src + EE;
    for (int e = t; e < EE; e += 256) atomicAdd(&sdeg[dst[e]], 1.f);
    __syncthreads();
    if (t < NN) sdinv[t] = rsqrtf(sdeg[t] + 1.f);
    __syncthreads();
    for (int e = t; e < EE; e += 256) {
        int s0 = src[e], d0 = dst[e];
        if ((d0 >> 6) == half)
            atomicAdd(&sA[(d0 - lo)*NN + s0], sdinv[s0] * sdinv[d0]);
    }
    if (t < 64) {
        int d = lo + t;
        atomicAdd(&sA[t*NN + d], sdinv[d] * sdinv[d]);
    }
    __syncthreads();
    bf16* Ab = g_A + (size_t)b * NN * NN + (size_t)lo * NN;
    for (int i = t; i < 64*NN/2; i += 256)
        ((__nv_bfloat162*)Ab)[i] = __floats2bfloat162_rn(sA[2*i], sA[2*i+1]);
}

// ---------------- K4/K7 (slot 4 PROFILED): Yt = (X @ Wt^T)^T, bf16 mma ----------
template<int KD, int SEL>
__global__ __launch_bounds__(128)
void k_gemm_tc() {
    const bf16* __restrict__ X  = SEL ? g_X1  : g_nf;
    const bf16* __restrict__ Wt = SEL ? g_W2t : g_W1t;
    bf16* __restrict__ Yt       = SEL ? g_H2t : g_H1t;
    __shared__ bf16 As[2][64][40];
    __shared__ bf16 Bs[2][64][40];
    int m0 = blockIdx.x * 64, n0 = blockIdx.y * 64;
    int t = threadIdx.x, lane = t & 31, warp = t >> 5;
    int gid = lane >> 2, tig = lane & 3;
    int wm = (warp >> 1) * 32, wn = (warp & 1) * 32;
    int aR = t >> 1, aH = (t & 1) * 16;   // thread covers cols [aH, aH+16)

    float acc[2][4][4];
#pragma unroll
    for (int i = 0; i < 2; i++)
#pragma unroll
        for (int j = 0; j < 4; j++)
#pragma unroll
            for (int q = 0; q < 4; q++) acc[i][j][q] = 0.f;

    const int NIT = KD / 32;
    uint4 pa0 = *(const uint4*)(X  + (size_t)(m0 + aR)*KD + aH);
    uint4 pa1 = *(const uint4*)(X  + (size_t)(m0 + aR)*KD + aH + 8);
    uint4 pb0 = *(const uint4*)(Wt + (size_t)(n0 + aR)*KD + aH);
    uint4 pb1 = *(const uint4*)(Wt + (size_t)(n0 + aR)*KD + aH + 8);
    *(uint4*)&As[0][aR][aH]     = pa0;
    *(uint4*)&As[0][aR][aH + 8] = pa1;
    *(uint4*)&Bs[0][aR][aH]     = pb0;
    *(uint4*)&Bs[0][aR][aH + 8] = pb1;

    for (int i = 0; i < NIT; i++) {
        __syncthreads();
        if (i + 1 < NIT) {
            int k0 = (i + 1) * 32;
            pa0 = *(const uint4*)(X  + (size_t)(m0 + aR)*KD + k0 + aH);
            pa1 = *(const uint4*)(X  + (size_t)(m0 + aR)*KD + k0 + aH + 8);
            pb0 = *(const uint4*)(Wt + (size_t)(n0 + aR)*KD + k0 + aH);
            pb1 = *(const uint4*)(Wt + (size_t)(n0 + aR)*KD + k0 + aH + 8);
        }
        mma_tile(As[i & 1], Bs[i & 1], acc, wm, wn, gid, tig);
        if (i + 1 < NIT) {
            int nx = (i + 1) & 1;
            *(uint4*)&As[nx][aR][aH]     = pa0;
            *(uint4*)&As[nx][aR][aH + 8] = pa1;
            *(uint4*)&Bs[nx][aR][aH]     = pb0;
            *(uint4*)&Bs[nx][aR][aH + 8] = pb1;
        }
    }

    // transposed epilogue through smem (reuse As storage): tile [64 m][68 n]
    __syncthreads();
    bf16* tp = &As[0][0][0];
#pragma unroll
    for (int i2 = 0; i2 < 2; i2++)
#pragma unroll
        for (int j = 0; j < 4; j++) {
            int r = wm + i2*16 + gid, cc = wn + j*8 + 2*tig;
            *(__nv_bfloat162*)&tp[r*68 + cc]     = __floats2bfloat162_rn(acc[i2][j][0], acc[i2][j][1]);
            *(__nv_bfloat162*)&tp[(r+8)*68 + cc] = __floats2bfloat162_rn(acc[i2][j][2], acc[i2][j][3]);
        }
    __syncthreads();
    int bb = m0 >> 7, nodeBase = m0 & 127;
    int rw = t >> 1, hf = (t & 1) * 32;
    bf16* outp = Yt + ((size_t)bb*GHD + n0 + rw) * NN + nodeBase + hf;
#pragma unroll
    for (int q = 0; q < 4; q++) {
        bf16 e[8];
#pragma unroll
        for (int k = 0; k < 8; k++) e[k] = tp[(hf + q*8 + k)*68 + rw];
        *(uint4*)&outp[q*8] = *(uint4*)e;
    }
}

// ---------------- K6/K8: relu(A_b @ H_b + bias) bf16 mma; POOL -> column mean ----
template<bool POOL>
__global__ __launch_bounds__(128)
void k_gcn_agg(const float* __restrict__ bias) {
    const bf16* __restrict__ Ht = POOL ? g_H2t : g_H1t;
    __shared__ bf16 As[2][64][40];
    __shared__ bf16 Bs[2][64][40];
    __shared__ float sred[64];
    int mt = blockIdx.x & 1, nt = blockIdx.x >> 1;
    int b = blockIdx.y;
    int t = threadIdx.x, lane = t & 31, warp = t >> 5;
    int gid = lane >> 2, tig = lane & 3;
    int wm = (warp >> 1) * 32, wn = (warp & 1) * 32;
    int aR = t >> 1, aH = (t & 1) * 16;

    if (POOL && t < 64) sred[t] = 0.f;

    const bf16* A = g_A + (size_t)b*NN*NN + (size_t)mt*64*NN;
    const bf16* B = Ht  + (size_t)b*GHD*NN + (size_t)nt*64*NN;

    float acc[2][4][4];
#pragma unroll
    for (int i = 0; i < 2; i++)
#pragma unroll
        for (int j = 0; j < 4; j++)
#pragma unroll
            for (int q = 0; q < 4; q++) acc[i][j][q] = 0.f;

    const int NIT = NN / 32;   // 4
    uint4 pa0 = *(const uint4*)(A + (size_t)aR*NN + aH);
    uint4 pa1 = *(const uint4*)(A + (size_t)aR*NN + aH + 8);
    uint4 pb0 = *(const uint4*)(B + (size_t)aR*NN + aH);
    uint4 pb1 = *(const uint4*)(B + (size_t)aR*NN + aH + 8);
    *(uint4*)&As[0][aR][aH]     = pa0;
    *(uint4*)&As[0][aR][aH + 8] = pa1;
    *(uint4*)&Bs[0][aR][aH]     = pb0;
    *(uint4*)&Bs[0][aR][aH + 8] = pb1;

    for (int i = 0; i < NIT; i++) {
        __syncthreads();
        if (i + 1 < NIT) {
            int k0 = (i + 1) * 32;
            pa0 = *(const uint4*)(A + (size_t)aR*NN + k0 + aH);
            pa1 = *(const uint4*)(A + (size_t)aR*NN + k0 + aH + 8);
            pb0 = *(const uint4*)(B + (size_t)aR*NN + k0 + aH);
            pb1 = *(const uint4*)(B + (size_t)aR*NN + k0 + aH + 8);
        }
        mma_tile(As[i & 1], Bs[i & 1], acc, wm, wn, gid, tig);
        if (i + 1 < NIT) {
            int nx = (i + 1) & 1;
            *(uint4*)&As[nx][aR][aH]     = pa0;
            *(uint4*)&As[nx][aR][aH + 8] = pa1;
            *(uint4*)&Bs[nx][aR][aH]     = pb0;
            *(uint4*)&Bs[nx][aR][aH + 8] = pb1;
        }
    }

    if (POOL) {
        float cs[4][2];
#pragma unroll
        for (int j = 0; j < 4; j++) { cs[j][0] = 0.f; cs[j][1] = 0.f; }
#pragma unroll
        for (int j = 0; j < 4; j++) {
            int cG = nt*64 + wn + j*8 + 2*tig;
            float b0 = bias[cG], b1 = bias[cG+1];
#pragma unroll
            for (int i2 = 0; i2 < 2; i2++) {
                cs[j][0] += fmaxf(acc[i2][j][0] + b0, 0.f) + fmaxf(acc[i2][j][2] + b0, 0.f);
                cs[j][1] += fmaxf(acc[i2][j][1] + b1, 0.f) + fmaxf(acc[i2][j][3] + b1, 0.f);
            }
        }
#pragma unroll
        for (int off = 4; off <= 16; off <<= 1)
#pragma unroll
            for (int j = 0; j < 4; j++) {
                cs[j][0] += __shfl_xor_sync(0xffffffffu, cs[j][0], off);
                cs[j][1] += __shfl_xor_sync(0xffffffffu, cs[j][1], off);
            }
        __syncthreads();   // sred init visible
        if (gid == 0) {
#pragma unroll
            for (int j = 0; j < 4; j++) {
                atomicAdd(&sred[wn + j*8 + 2*tig],     cs[j][0]);
                atomicAdd(&sred[wn + j*8 + 2*tig + 1], cs[j][1]);
            }
        }
        __syncthreads();
        if (t < 64)
            atomicAdd(&g_pooled[b*GHD + nt*64 + t], sred[t] * (1.f/128.f));
    } else {
#pragma unroll
        for (int i2 = 0; i2 < 2; i2++)
#pragma unroll
            for (int j = 0; j < 4; j++) {
                int rnode = mt*64 + wm + i2*16 + gid;
                int cG = nt*64 + wn + j*8 + 2*tig;
                float b0 = bias[cG], b1 = bias[cG+1];
                float v00 = fmaxf(acc[i2][j][0] + b0, 0.f);
                float v01 = fmaxf(acc[i2][j][1] + b1, 0.f);
                float v10 = fmaxf(acc[i2][j][2] + b0, 0.f);
                float v11 = fmaxf(acc[i2][j][3] + b1, 0.f);
                *(__nv_bfloat162*)&g_X1[((size_t)(b*NN + rnode))*GHD + cG]     = __floats2bfloat162_rn(v00, v01);
                *(__nv_bfloat162*)&g_X1[((size_t)(b*NN + rnode + 8))*GHD + cG] = __floats2bfloat162_rn(v10, v11);
            }
    }
}

// ---------------- K9: MLP head ----------------
__global__ __launch_bounds__(256)
void k_head(const float* __restrict__ lh, const float* __restrict__ Wf1,
            const float* __restrict__ bf1, const float* __restrict__ Wf2,
            const float* __restrict__ bf2, float* __restrict__ out) {
    __shared__ float xin[HH + GHD];
    __shared__ float sh[FHD];
    int b = blockIdx.x, t = threadIdx.x;   // 256
    for (int i = t; i < HH; i += 256) xin[i] = lh[((size_t)b*SS)*HH + i];
    if (t < GHD) xin[HH + t] = g_pooled[b*GHD + t];
    __syncthreads();
    float a0 = 0.f, a1 = 0.f, a2 = 0.f, a3 = 0.f;
    for (int k = 0; k < HH + GHD; k += 4) {
        a0 += xin[k+0] * Wf1[(k+0)*FHD + t];
        a1 += xin[k+1] * Wf1[(k+1)*FHD + t];
        a2 += xin[k+2] * Wf1[(k+2)*FHD + t];
        a3 += xin[k+3] * Wf1[(k+3)*FHD + t];
    }
    sh[t] = fmaxf(a0 + a1 + a2 + a3 + bf1[t], 0.f);
    __syncthreads();
    int w = t >> 5, lane = t & 31;
    if (w < 2) {
        float s = 0.f;
        for (int k = lane; k < FHD; k += 32) s += sh[k] * Wf2[k*2 + w];
#pragma unroll
        for (int o = 16; o; o >>= 1) s += __shfl_xor_sync(0xffffffffu, s, o);
        if (lane == 0) out[b*2 + w] = s + bf2[w];
    }
}

// ---------------- launch: ONLY kernel launches ----------------
extern "C" void kernel_launch(void* const* d_in, const int* in_sizes, int n_in,
                              void* d_out, int out_size) {
    const float* lh     = (const float*)d_in[0];
    const int*   submap = (const int*)  d_in[1];
    const int*   ei     = (const int*)  d_in[2];
    // d_in[3] = num_nodes (always 128, unused)
    const float* wr  = (const float*)d_in[4];
    const float* br  = (const float*)d_in[5];
    const float* W1  = (const float*)d_in[6];
    const float* b1  = (const float*)d_in[7];
    const float* W2  = (const float*)d_in[8];
    const float* b2  = (const float*)d_in[9];
    const float* Wf1 = (const float*)d_in[10];
    const float* bf1 = (const float*)d_in[11];
    const float* Wf2 = (const float*)d_in[12];
    const float* bf2 = (const float*)d_in[13];
    float* out = (float*)d_out;

    k_sortc<<<BB, 128>>>(submap);                           // 1 counts+sort
    k_prepWz<<<(HH*GHD + GHD*GHD + BB*GHD + 255)/256, 256>>>(W1, W2); // 2
    dim3 gsc(NGRP, BB);                                     // (16, 64)
    k_scatter6<<<gsc, 192>>>(lh, wr, br);                   // 3 fused gate+scatter
    dim3 gg1(BNN/64, 2);
    k_gemm_tc<HH, 0><<<gg1, 128>>>();                       // 4 <- profiled slot
    k_adj<<<2*BB, 256>>>(ei);                               // 5
    dim3 gag(4, BB);
    k_gcn_agg<false><<<gag, 128>>>(b1);                     // 6
    dim3 gg2(BNN/64, 2);
    k_gemm_tc<GHD, 1><<<gg2, 128>>>();                      // 7
    k_gcn_agg<true><<<gag, 128>>>(b2);                      // 8
    k_head<<<BB, 256>>>(lh, Wf1, bf1, Wf2, bf2, out);       // 9
}

// round 12
// speedup vs baseline: 1.9892x; 1.0198x over previous
#include <cuda_runtime.h>
#include <cuda_bf16.h>
#include <math.h>
#include <stdint.h>

// ---------------- problem constants ----------------
#define BB 64
#define SS 512
#define HH 768
#define NN 128
#define EE 1024
#define GHD 128
#define FHD 256
#define BNN (BB*NN)          // 8192

typedef __nv_bfloat16 bf16;

// ---------------- device scratch (no allocation allowed) ----------------
__device__ int   g_perm[BB*SS];
__device__ int   g_soff[BB*(NN+1)];
__device__ bf16  g_nf[BNN*HH];            // node features bf16, 12.6 MB
__device__ bf16  g_A[BB*NN*NN];           // normalized adjacency bf16
__device__ bf16  g_W1t[GHD*HH];           // W1 transposed [n][k] bf16
__device__ bf16  g_W2t[GHD*GHD];          // W2 transposed [n][k] bf16
__device__ bf16  g_H1t[BB*GHD*NN];        // H1 transposed per batch [feat][node]
__device__ bf16  g_X1[BNN*GHD];           // X1 normal [row][feat]
__device__ bf16  g_H2t[BB*GHD*NN];        // H2 transposed per batch
__device__ float g_pooled[BB*GHD];

// ---------------- cp.async helpers ----------------
__device__ __forceinline__ void cp16(uint32_t saddr, const void* gptr) {
    asm volatile("cp.async.cg.shared.global [%0], [%1], 16;" :: "r"(saddr), "l"(gptr));
}
__device__ __forceinline__ void cp_commit() {
    asm volatile("cp.async.commit_group;");
}
__device__ __forceinline__ void cp_wait2() {
    asm volatile("cp.async.wait_group 2;");
}

// ---------------- bf16 mma m16n8k16 ----------------
__device__ __forceinline__ void mma_bf16(float* d, uint32_t a0, uint32_t a1,
                                         uint32_t a2, uint32_t a3,
                                         uint32_t b0, uint32_t b1) {
    asm volatile(
        "mma.sync.aligned.m16n8k16.row.col.f32.bf16.bf16.f32 "
        "{%0,%1,%2,%3}, {%4,%5,%6,%7}, {%8,%9}, {%0,%1,%2,%3};"
        : "+f"(d[0]), "+f"(d[1]), "+f"(d[2]), "+f"(d[3])
        : "r"(a0), "r"(a1), "r"(a2), "r"(a3), "r"(b0), "r"(b1));
}

// one BK=32 tile of MMA work; As/Bs are [64][40] bf16
__device__ __forceinline__ void mma_tile(const bf16 (*Ac)[40], const bf16 (*Bc)[40],
                                         float acc[2][4][4],
                                         int wm, int wn, int gid, int tig) {
#pragma unroll
    for (int kh = 0; kh < 32; kh += 16) {
        uint32_t a[2][4];
#pragma unroll
        for (int i2 = 0; i2 < 2; i2++) {
            int m = wm + i2*16;
            a[i2][0] = *(const uint32_t*)&Ac[m+gid  ][kh + 2*tig];
            a[i2][1] = *(const uint32_t*)&Ac[m+gid+8][kh + 2*tig];
            a[i2][2] = *(const uint32_t*)&Ac[m+gid  ][kh + 2*tig + 8];
            a[i2][3] = *(const uint32_t*)&Ac[m+gid+8][kh + 2*tig + 8];
        }
#pragma unroll
        for (int j = 0; j < 4; j++) {
            uint32_t b0 = *(const uint32_t*)&Bc[wn+j*8+gid][kh + 2*tig];
            uint32_t b1 = *(const uint32_t*)&Bc[wn+j*8+gid][kh + 2*tig + 8];
#pragma unroll
            for (int i2 = 0; i2 < 2; i2++)
                mma_bf16(acc[i2][j], a[i2][0], a[i2][1], a[i2][2], a[i2][3], b0, b1);
        }
    }
}

// ---------------- K1: counts + deterministic counting sort of tokens by node ------
__global__ __launch_bounds__(128)
void k_sortc(const int* __restrict__ submap) {
    __shared__ int snode[SS];
    __shared__ int scnt[NN];
    __shared__ int soff[NN+1];
    int b = blockIdx.x, t = threadIdx.x;   // 128 threads
#pragma unroll
    for (int u = 0; u < 4; u++) snode[t + u*128] = submap[b*SS + t + u*128];
    scnt[t] = 0;
    __syncthreads();
#pragma unroll
    for (int u = 0; u < 4; u++) atomicAdd(&scnt[snode[t + u*128]], 1);
    __syncthreads();
    if (t == 0) {
        int run = 0;
        for (int n = 0; n < NN; n++) { soff[n] = run; run += scnt[n]; }
        soff[NN] = SS;
    }
    __syncthreads();
    {
        int o = soff[t];
        for (int s = 0; s < SS; s++)
            if (snode[s] == t) g_perm[b*SS + o++] = s;
        g_soff[b*(NN+1) + t] = soff[t];
        if (t == 0) g_soff[b*(NN+1) + NN] = SS;
    }
}

// ---------------- K2: convert W1/W2 to transposed bf16 + zero pooled -------------
__global__ void k_prepWz(const float* __restrict__ W1, const float* __restrict__ W2) {
    int idx = blockIdx.x * blockDim.x + threadIdx.x;
    if (idx < HH*GHD) {
        int k = idx >> 7, n = idx & 127;
        g_W1t[n*HH + k] = __float2bfloat16(W1[idx]);
    } else if (idx < HH*GHD + GHD*GHD) {
        int i2 = idx - HH*GHD;
        int k = i2 >> 7, n = i2 & 127;
        g_W2t[n*GHD + k] = __float2bfloat16(W2[i2]);
    } else {
        int i3 = idx - HH*GHD - GHD*GHD;
        if (i3 < BB*GHD) g_pooled[i3] = 0.f;
    }
}

// ---------------- K3: FUSED gate + sorted segment-mean -----------------------
#define NGRP 16
#define NPG  (NN/NGRP)     // 8 nodes per group
__global__ __launch_bounds__(192)
void k_scatter6(const float* __restrict__ lh, const float* __restrict__ wr,
                const float* __restrict__ brp) {
    __shared__ int    sperm[SS];
    __shared__ float  sg[SS];
    __shared__ int    ssoff[NPG + 1];
    __shared__ float4 swr[HH/4];         // 192 float4 = wr
    int ng = blockIdx.x;
    int b  = blockIdx.y;
    int t  = threadIdx.x;
    if (t < NPG + 1) ssoff[t] = g_soff[b*(NN+1) + ng*NPG + t];
    swr[t] = ((const float4*)wr)[t];     // exactly 192 threads
    __syncthreads();
    int i0 = ssoff[0], i1 = ssoff[NPG];
    for (int i = i0 + t; i < i1; i += 192)
        sperm[i - i0] = g_perm[b*SS + i];
    __syncthreads();

    const float4* lb = reinterpret_cast<const float4*>(lh + (size_t)b * SS * HH);
    float brv = __ldg(brp);
    int w = t >> 5, lane = t & 31;
    // Phase A: gates (one token per warp, round-robin)
    for (int i = i0 + w; i < i1; i += 6) {
        const float4* row = lb + (size_t)sperm[i - i0] * 192;
        float d = 0.f;
#pragma unroll
        for (int q = 0; q < 6; q++) {
            float4 v  = row[lane + q*32];
            float4 wv = swr[lane + q*32];
            d += v.x*wv.x + v.y*wv.y + v.z*wv.z + v.w*wv.w;
        }
#pragma unroll
        for (int o = 16; o; o >>= 1) d += __shfl_xor_sync(0xffffffffu, d, o);
        if (lane == 0) sg[i - i0] = 1.f / (1.f + __expf(-(d + brv)));
    }
    __syncthreads();

    // Phase B: weighted accumulate per node (rows L2-resident from phase A)
    const float4* base = lb + t;
    bf16* outp = g_nf + ((size_t)(b * NN + ng * NPG)) * HH + t*4;
#pragma unroll 1
    for (int n = 0; n < NPG; n++) {
        int j0 = ssoff[n] - i0, j1 = ssoff[n+1] - i0;
        int cnt = j1 - j0;
        float inv = 1.f / (float)(cnt < 1 ? 1 : cnt);
        float ax = 0.f, ay = 0.f, az = 0.f, aw = 0.f;
        int i = j0;
        for (; i + 4 <= j1; i += 4) {
            float4 v0 = base[(size_t)sperm[i+0] * 192];
            float4 v1 = base[(size_t)sperm[i+1] * 192];
            float4 v2 = base[(size_t)sperm[i+2] * 192];
            float4 v3 = base[(size_t)sperm[i+3] * 192];
            float w0 = sg[i+0], w1 = sg[i+1], w2 = sg[i+2], w3 = sg[i+3];
            ax += w0*v0.x; ay += w0*v0.y; az += w0*v0.z; aw += w0*v0.w;
            ax += w1*v1.x; ay += w1*v1.y; az += w1*v1.z; aw += w1*v1.w;
            ax += w2*v2.x; ay += w2*v2.y; az += w2*v2.z; aw += w2*v2.w;
            ax += w3*v3.x; ay += w3*v3.y; az += w3*v3.z; aw += w3*v3.w;
        }
        for (; i < j1; i++) {
            float4 v = base[(size_t)sperm[i] * 192];
            float ww = sg[i];
            ax += ww*v.x; ay += ww*v.y; az += ww*v.z; aw += ww*v.w;
        }
        __nv_bfloat162 o0 = __floats2bfloat162_rn(ax*inv, ay*inv);
        __nv_bfloat162 o1 = __floats2bfloat162_rn(az*inv, aw*inv);
        *(__nv_bfloat162*)(outp + (size_t)n*HH)     = o0;
        *(__nv_bfloat162*)(outp + (size_t)n*HH + 2) = o1;
    }
}

// ---------------- K5: dense normalized adjacency (bf16 out), 2 CTAs/batch --------
__global__ __launch_bounds__(256)
void k_adj(const int* __restrict__ ei) {
    __shared__ float sA[64*NN];          // 32KB
    __shared__ float sdeg[NN];
    __shared__ float sdinv[NN];
    int b = blockIdx.x >> 1;
    int half = blockIdx.x & 1;
    int lo = half * 64;
    int t = threadIdx.x;                 // 256 threads
    if (t < NN) sdeg[t] = 0.f;
    for (int i = t; i < 64*NN/4; i += 256)
        ((float4*)sA)[i] = make_float4(0.f,0.f,0.f,0.f);
    __syncthreads();
    const int* src = ei + (size_t)b * 2 * EE;
    const int* dst = src + EE;
    for (int e = t; e < EE; e += 256) atomicAdd(&sdeg[dst[e]], 1.f);
    __syncthreads();
    if (t < NN) sdinv[t] = rsqrtf(sdeg[t] + 1.f);
    __syncthreads();
    for (int e = t; e < EE; e += 256) {
        int s0 = src[e], d0 = dst[e];
        if ((d0 >> 6) == half)
            atomicAdd(&sA[(d0 - lo)*NN + s0], sdinv[s0] * sdinv[d0]);
    }
    if (t < 64) {
        int d = lo + t;
        atomicAdd(&sA[t*NN + d], sdinv[d] * sdinv[d]);
    }
    __syncthreads();
    bf16* Ab = g_A + (size_t)b * NN * NN + (size_t)lo * NN;
    for (int i = t; i < 64*NN/2; i += 256)
        ((__nv_bfloat162*)Ab)[i] = __floats2bfloat162_rn(sA[2*i], sA[2*i+1]);
}

// ---------------- K4/K7 (slot 4 PROFILED): Yt = (X @ Wt^T)^T, 4-stage cp.async ---
// Tail-safe: empty commit keeps group count advancing so wait_group 2 always
// completes the stage being consumed.
template<int KD, int SEL>
__global__ __launch_bounds__(128)
void k_gemm_tc() {
    const bf16* __restrict__ X  = SEL ? g_X1  : g_nf;
    const bf16* __restrict__ Wt = SEL ? g_W2t : g_W1t;
    bf16* __restrict__ Yt       = SEL ? g_H2t : g_H1t;
    __shared__ bf16 As[4][64][40];
    __shared__ bf16 Bs[4][64][40];
    int m0 = blockIdx.x * 64, n0 = blockIdx.y * 64;
    int t = threadIdx.x, lane = t & 31, warp = t >> 5;
    int gid = lane >> 2, tig = lane & 3;
    int wm = (warp >> 1) * 32, wn = (warp & 1) * 32;
    int aR = t >> 1, aH = (t & 1) * 16;   // thread covers cols [aH, aH+16)

    const bf16* Xr = X  + (size_t)(m0 + aR)*KD + aH;
    const bf16* Wr = Wt + (size_t)(n0 + aR)*KD + aH;

    float acc[2][4][4];
#pragma unroll
    for (int i = 0; i < 2; i++)
#pragma unroll
        for (int j = 0; j < 4; j++)
#pragma unroll
            for (int q = 0; q < 4; q++) acc[i][j][q] = 0.f;

    const int NIT = KD / 32;

#define GEMM_ISSUE(ii) do {                                              \
        int st_ = (ii) & 3; int k0_ = (ii) * 32;                         \
        uint32_t sa_ = (uint32_t)__cvta_generic_to_shared(&As[st_][aR][aH]); \
        uint32_t sb_ = (uint32_t)__cvta_generic_to_shared(&Bs[st_][aR][aH]); \
        cp16(sa_,      Xr + k0_);                                        \
        cp16(sa_ + 16, Xr + k0_ + 8);                                    \
        cp16(sb_,      Wr + k0_);                                        \
        cp16(sb_ + 16, Wr + k0_ + 8);                                    \
        cp_commit();                                                     \
    } while (0)

    GEMM_ISSUE(0); GEMM_ISSUE(1); GEMM_ISSUE(2);

    for (int i = 0; i < NIT; i++) {
        cp_wait2();
        __syncthreads();
        if (i + 3 < NIT) GEMM_ISSUE(i + 3);
        else cp_commit();                 // empty group: tail-safe accounting
        mma_tile(As[i & 3], Bs[i & 3], acc, wm, wn, gid, tig);
    }

    // transposed epilogue through smem (reuse As storage): tile [64 m][68 n]
    __syncthreads();
    bf16* tp = &As[0][0][0];
#pragma unroll
    for (int i2 = 0; i2 < 2; i2++)
#pragma unroll
        for (int j = 0; j < 4; j++) {
            int r = wm + i2*16 + gid, cc = wn + j*8 + 2*tig;
            *(__nv_bfloat162*)&tp[r*68 + cc]     = __floats2bfloat162_rn(acc[i2][j][0], acc[i2][j][1]);
            *(__nv_bfloat162*)&tp[(r+8)*68 + cc] = __floats2bfloat162_rn(acc[i2][j][2], acc[i2][j][3]);
        }
    __syncthreads();
    int bb = m0 >> 7, nodeBase = m0 & 127;
    int rw = t >> 1, hf = (t & 1) * 32;
    bf16* outp = Yt + ((size_t)bb*GHD + n0 + rw) * NN + nodeBase + hf;
#pragma unroll
    for (int q = 0; q < 4; q++) {
        bf16 e[8];
#pragma unroll
        for (int k = 0; k < 8; k++) e[k] = tp[(hf + q*8 + k)*68 + rw];
        *(uint4*)&outp[q*8] = *(uint4*)e;
    }
}

// ---------------- K6/K8: relu(A_b @ H_b + bias), 4-stage cp.async; POOL mean -----
template<bool POOL>
__global__ __launch_bounds__(128)
void k_gcn_agg(const float* __restrict__ bias) {
    const bf16* __restrict__ Ht = POOL ? g_H2t : g_H1t;
    __shared__ bf16 As[4][64][40];
    __shared__ bf16 Bs[4][64][40];
    __shared__ float sred[64];
    int mt = blockIdx.x & 1, nt = blockIdx.x >> 1;
    int b = blockIdx.y;
    int t = threadIdx.x, lane = t & 31, warp = t >> 5;
    int gid = lane >> 2, tig = lane & 3;
    int wm = (warp >> 1) * 32, wn = (warp & 1) * 32;
    int aR = t >> 1, aH = (t & 1) * 16;

    if (POOL && t < 64) sred[t] = 0.f;

    const bf16* Ar = g_A + (size_t)b*NN*NN  + (size_t)(mt*64 + aR)*NN + aH;
    const bf16* Br = Ht  + (size_t)b*GHD*NN + (size_t)(nt*64 + aR)*NN + aH;

    float acc[2][4][4];
#pragma unroll
    for (int i = 0; i < 2; i++)
#pragma unroll
        for (int j = 0; j < 4; j++)
#pragma unroll
            for (int q = 0; q < 4; q++) acc[i][j][q] = 0.f;

    const int NIT = NN / 32;   // 4

#define AGG_ISSUE(ii) do {                                               \
        int st_ = (ii) & 3; int k0_ = (ii) * 32;                         \
        uint32_t sa_ = (uint32_t)__cvta_generic_to_shared(&As[st_][aR][aH]); \
        uint32_t sb_ = (uint32_t)__cvta_generic_to_shared(&Bs[st_][aR][aH]); \
        cp16(sa_,      Ar + k0_);                                        \
        cp16(sa_ + 16, Ar + k0_ + 8);                                    \
        cp16(sb_,      Br + k0_);                                        \
        cp16(sb_ + 16, Br + k0_ + 8);                                    \
        cp_commit();                                                     \
    } while (0)

    AGG_ISSUE(0); AGG_ISSUE(1); AGG_ISSUE(2);

    for (int i = 0; i < NIT; i++) {
        cp_wait2();
        __syncthreads();
        if (i + 3 < NIT) AGG_ISSUE(i + 3);
        else cp_commit();                 // empty group: tail-safe accounting
        mma_tile(As[i & 3], Bs[i & 3], acc, wm, wn, gid, tig);
    }

    if (POOL) {
        float cs[4][2];
#pragma unroll
        for (int j = 0; j < 4; j++) { cs[j][0] = 0.f; cs[j][1] = 0.f; }
#pragma unroll
        for (int j = 0; j < 4; j++) {
            int cG = nt*64 + wn + j*8 + 2*tig;
            float b0 = bias[cG], b1 = bias[cG+1];
#pragma unroll
            for (int i2 = 0; i2 < 2; i2++) {
                cs[j][0] += fmaxf(acc[i2][j][0] + b0, 0.f) + fmaxf(acc[i2][j][2] + b0, 0.f);
                cs[j][1] += fmaxf(acc[i2][j][1] + b1, 0.f) + fmaxf(acc[i2][j][3] + b1, 0.f);
            }
        }
#pragma unroll
        for (int off = 4; off <= 16; off <<= 1)
#pragma unroll
            for (int j = 0; j < 4; j++) {
                cs[j][0] += __shfl_xor_sync(0xffffffffu, cs[j][0], off);
                cs[j][1] += __shfl_xor_sync(0xffffffffu, cs[j][1], off);
            }
        __syncthreads();   // sred init visible
        if (gid == 0) {
#pragma unroll
            for (int j = 0; j < 4; j++) {
                atomicAdd(&sred[wn + j*8 + 2*tig],     cs[j][0]);
                atomicAdd(&sred[wn + j*8 + 2*tig + 1], cs[j][1]);
            }
        }
        __syncthreads();
        if (t < 64)
            atomicAdd(&g_pooled[b*GHD + nt*64 + t], sred[t] * (1.f/128.f));
    } else {
#pragma unroll
        for (int i2 = 0; i2 < 2; i2++)
#pragma unroll
            for (int j = 0; j < 4; j++) {
                int rnode = mt*64 + wm + i2*16 + gid;
                int cG = nt*64 + wn + j*8 + 2*tig;
                float b0 = bias[cG], b1 = bias[cG+1];
                float v00 = fmaxf(acc[i2][j][0] + b0, 0.f);
                float v01 = fmaxf(acc[i2][j][1] + b1, 0.f);
                float v10 = fmaxf(acc[i2][j][2] + b0, 0.f);
                float v11 = fmaxf(acc[i2][j][3] + b1, 0.f);
                *(__nv_bfloat162*)&g_X1[((size_t)(b*NN + rnode))*GHD + cG]     = __floats2bfloat162_rn(v00, v01);
                *(__nv_bfloat162*)&g_X1[((size_t)(b*NN + rnode + 8))*GHD + cG] = __floats2bfloat162_rn(v10, v11);
            }
    }
}

// ---------------- K9: MLP head ----------------
__global__ __launch_bounds__(256)
void k_head(const float* __restrict__ lh, const float* __restrict__ Wf1,
            const float* __restrict__ bf1, const float* __restrict__ Wf2,
            const float* __restrict__ bf2, float* __restrict__ out) {
    __shared__ float xin[HH + GHD];
    __shared__ float sh[FHD];
    int b = blockIdx.x, t = threadIdx.x;   // 256
    for (int i = t; i < HH; i += 256) xin[i] = lh[((size_t)b*SS)*HH + i];
    if (t < GHD) xin[HH + t] = g_pooled[b*GHD + t];
    __syncthreads();
    float a0 = 0.f, a1 = 0.f, a2 = 0.f, a3 = 0.f;
    for (int k = 0; k < HH + GHD; k += 4) {
        a0 += xin[k+0] * Wf1[(k+0)*FHD + t];
        a1 += xin[k+1] * Wf1[(k+1)*FHD + t];
        a2 += xin[k+2] * Wf1[(k+2)*FHD + t];
        a3 += xin[k+3] * Wf1[(k+3)*FHD + t];
    }
    sh[t] = fmaxf(a0 + a1 + a2 + a3 + bf1[t], 0.f);
    __syncthreads();
    int w = t >> 5, lane = t & 31;
    if (w < 2) {
        float s = 0.f;
        for (int k = lane; k < FHD; k += 32) s += sh[k] * Wf2[k*2 + w];
#pragma unroll
        for (int o = 16; o; o >>= 1) s += __shfl_xor_sync(0xffffffffu, s, o);
        if (lane == 0) out[b*2 + w] = s + bf2[w];
    }
}

// ---------------- launch: ONLY kernel launches ----------------
extern "C" void kernel_launch(void* const* d_in, const int* in_sizes, int n_in,
                              void* d_out, int out_size) {
    const float* lh     = (const float*)d_in[0];
    const int*   submap = (const int*)  d_in[1];
    const int*   ei     = (const int*)  d_in[2];
    // d_in[3] = num_nodes (always 128, unused)
    const float* wr  = (const float*)d_in[4];
    const float* br  = (const float*)d_in[5];
    const float* W1  = (const float*)d_in[6];
    const float* b1  = (const float*)d_in[7];
    const float* W2  = (const float*)d_in[8];
    const float* b2  = (const float*)d_in[9];
    const float* Wf1 = (const float*)d_in[10];
    const float* bf1 = (const float*)d_in[11];
    const float* Wf2 = (const float*)d_in[12];
    const float* bf2 = (const float*)d_in[13];
    float* out = (float*)d_out;

    k_sortc<<<BB, 128>>>(submap);                           // 1 counts+sort
    k_prepWz<<<(HH*GHD + GHD*GHD + BB*GHD + 255)/256, 256>>>(W1, W2); // 2
    dim3 gsc(NGRP, BB);                                     // (16, 64)
    k_scatter6<<<gsc, 192>>>(lh, wr, br);                   // 3 fused gate+scatter
    dim3 gg1(BNN/64, 2);
    k_gemm_tc<HH, 0><<<gg1, 128>>>();                       // 4 <- profiled slot
    k_adj<<<2*BB, 256>>>(ei);                               // 5
    dim3 gag(4, BB);
    k_gcn_agg<false><<<gag, 128>>>(b1);                     // 6
    dim3 gg2(BNN/64, 2);
    k_gemm_tc<GHD, 1><<<gg2, 128>>>();                      // 7
    k_gcn_agg<true><<<gag, 128>>>(b2);                      // 8
    k_head<<<BB, 256>>>(lh, Wf1, bf1, Wf2, bf2, out);       // 9
}

// round 14
// speedup vs baseline: 2.0427x; 1.0269x over previous
#include <cuda_runtime.h>
#include <cuda_bf16.h>
#include <math.h>
#include <stdint.h>

// ---------------- problem constants ----------------
#define BB 64
#define SS 512
#define HH 768
#define NN 128
#define EE 1024
#define GHD 128
#define FHD 256
#define BNN (BB*NN)          // 8192

typedef __nv_bfloat16 bf16;

// ---------------- device scratch (no allocation allowed) ----------------
__device__ int   g_perm[BB*SS];
__device__ int   g_soff[BB*(NN+1)];
__device__ bf16  g_nf[BNN*HH];            // node features bf16
__device__ bf16  g_A[BB*NN*NN];           // normalized adjacency bf16
__device__ bf16  g_W1t[GHD*HH];           // W1 transposed [n][k]
__device__ bf16  g_W2t[GHD*GHD];          // W2 transposed [n][k]
__device__ bf16  g_H1t[BB*GHD*NN];        // H1 transposed per batch [feat][node]
__device__ bf16  g_X1[BNN*GHD];           // X1 [row][feat]
__device__ bf16  g_H2t[BB*GHD*NN];        // H2 transposed per batch
__device__ float g_pooled[BB*GHD];

// ---------------- cp.async helpers ----------------
__device__ __forceinline__ void cp16(uint32_t saddr, const void* gptr) {
    asm volatile("cp.async.cg.shared.global [%0], [%1], 16;" :: "r"(saddr), "l"(gptr));
}
__device__ __forceinline__ void cp_commit() {
    asm volatile("cp.async.commit_group;");
}
__device__ __forceinline__ void cp_wait2() {
    asm volatile("cp.async.wait_group 2;");
}

// ---------------- bf16 mma m16n8k16 ----------------
__device__ __forceinline__ void mma_bf16(float* d, uint32_t a0, uint32_t a1,
                                         uint32_t a2, uint32_t a3,
                                         uint32_t b0, uint32_t b1) {
    asm volatile(
        "mma.sync.aligned.m16n8k16.row.col.f32.bf16.bf16.f32 "
        "{%0,%1,%2,%3}, {%4,%5,%6,%7}, {%8,%9}, {%0,%1,%2,%3};"
        : "+f"(d[0]), "+f"(d[1]), "+f"(d[2]), "+f"(d[3])
        : "r"(a0), "r"(a1), "r"(a2), "r"(a3), "r"(b0), "r"(b1));
}

// one BK=32 tile; A is [32][40], B is [64][40]; warp tile 16x32
__device__ __forceinline__ void mma_tile32(const bf16 (*Ac)[40], const bf16 (*Bc)[40],
                                           float acc[4][4],
                                           int wm, int wn, int gid, int tig) {
#pragma unroll
    for (int kh = 0; kh < 32; kh += 16) {
        uint32_t a0 = *(const uint32_t*)&Ac[wm+gid  ][kh + 2*tig];
        uint32_t a1 = *(const uint32_t*)&Ac[wm+gid+8][kh + 2*tig];
        uint32_t a2 = *(const uint32_t*)&Ac[wm+gid  ][kh + 2*tig + 8];
        uint32_t a3 = *(const uint32_t*)&Ac[wm+gid+8][kh + 2*tig + 8];
#pragma unroll
        for (int j = 0; j < 4; j++) {
            uint32_t b0 = *(const uint32_t*)&Bc[wn+j*8+gid][kh + 2*tig];
            uint32_t b1 = *(const uint32_t*)&Bc[wn+j*8+gid][kh + 2*tig + 8];
            mma_bf16(acc[j], a0, a1, a2, a3, b0, b1);
        }
    }
}

// ---------------- K1: counts + deterministic counting sort ----------------
__global__ __launch_bounds__(128)
void k_sortc(const int* __restrict__ submap) {
    __shared__ int snode[SS];
    __shared__ int scnt[NN];
    __shared__ int soff[NN+1];
    int b = blockIdx.x, t = threadIdx.x;   // 128 threads
#pragma unroll
    for (int u = 0; u < 4; u++) snode[t + u*128] = submap[b*SS + t + u*128];
    scnt[t] = 0;
    __syncthreads();
#pragma unroll
    for (int u = 0; u < 4; u++) atomicAdd(&scnt[snode[t + u*128]], 1);
    __syncthreads();
    if (t == 0) {
        int run = 0;
        for (int n = 0; n < NN; n++) { soff[n] = run; run += scnt[n]; }
        soff[NN] = SS;
    }
    __syncthreads();
    {
        int o = soff[t];
        for (int s = 0; s < SS; s++)
            if (snode[s] == t) g_perm[b*SS + o++] = s;
        g_soff[b*(NN+1) + t] = soff[t];
        if (t == 0) g_soff[b*(NN+1) + NN] = SS;
    }
}

// ---------------- K2: convert W1/W2 to transposed bf16 + zero pooled -------------
__global__ void k_prepWz(const float* __restrict__ W1, const float* __restrict__ W2) {
    int idx = blockIdx.x * blockDim.x + threadIdx.x;
    if (idx < HH*GHD) {
        int k = idx >> 7, n = idx & 127;
        g_W1t[n*HH + k] = __float2bfloat16(W1[idx]);
    } else if (idx < HH*GHD + GHD*GHD) {
        int i2 = idx - HH*GHD;
        int k = i2 >> 7, n = i2 & 127;
        g_W2t[n*GHD + k] = __float2bfloat16(W2[i2]);
    } else {
        int i3 = idx - HH*GHD - GHD*GHD;
        if (i3 < BB*GHD) g_pooled[i3] = 0.f;
    }
}

// ---------------- K3: FUSED (gate+scatter) and adjacency in one launch ----------
// grid (NGRP+2, BB), block 192. ng < NGRP: scatter group; else adjacency half.
#define NGRP 16
#define NPG  (NN/NGRP)     // 8 nodes per group
__global__ __launch_bounds__(192)
void k_scatadj(const float* __restrict__ lh, const float* __restrict__ wr,
               const float* __restrict__ brp, const int* __restrict__ ei) {
    __shared__ float  sA[64*NN];         // 32KB (adj branch)
    __shared__ float  sdeg[NN];
    __shared__ float  sdinv[NN];
    __shared__ int    sperm[SS];
    __shared__ float  sg[SS];
    __shared__ int    ssoff[NPG + 1];
    __shared__ float4 swr[HH/4];
    int ng = blockIdx.x;
    int b  = blockIdx.y;
    int t  = threadIdx.x;

    if (ng >= NGRP) {
        // ---- adjacency half ----
        int half = ng - NGRP;
        int lo = half * 64;
        if (t < NN) sdeg[t] = 0.f;
        for (int i = t; i < 64*NN/4; i += 192)
            ((float4*)sA)[i] = make_float4(0.f,0.f,0.f,0.f);
        __syncthreads();
        const int* src = ei + (size_t)b * 2 * EE;
        const int* dst = src + EE;
        for (int e = t; e < EE; e += 192) atomicAdd(&sdeg[dst[e]], 1.f);
        __syncthreads();
        if (t < NN) sdinv[t] = rsqrtf(sdeg[t] + 1.f);
        __syncthreads();
        for (int e = t; e < EE; e += 192) {
            int s0 = src[e], d0 = dst[e];
            if ((d0 >> 6) == half)
                atomicAdd(&sA[(d0 - lo)*NN + s0], sdinv[s0] * sdinv[d0]);
        }
        if (t < 64) {
            int d = lo + t;
            atomicAdd(&sA[t*NN + d], sdinv[d] * sdinv[d]);
        }
        __syncthreads();
        bf16* Ab = g_A + (size_t)b * NN * NN + (size_t)lo * NN;
        for (int i = t; i < 64*NN/2; i += 192)
            ((__nv_bfloat162*)Ab)[i] = __floats2bfloat162_rn(sA[2*i], sA[2*i+1]);
        return;
    }

    // ---- fused gate + sorted segment-mean ----
    if (t < NPG + 1) ssoff[t] = g_soff[b*(NN+1) + ng*NPG + t];
    swr[t] = ((const float4*)wr)[t];     // exactly 192 threads
    __syncthreads();
    int i0 = ssoff[0], i1 = ssoff[NPG];
    for (int i = i0 + t; i < i1; i += 192)
        sperm[i - i0] = g_perm[b*SS + i];
    __syncthreads();

    const float4* lb = reinterpret_cast<const float4*>(lh + (size_t)b * SS * HH);
    float brv = __ldg(brp);
    int w = t >> 5, lane = t & 31;
    for (int i = i0 + w; i < i1; i += 6) {
        const float4* row = lb + (size_t)sperm[i - i0] * 192;
        float d = 0.f;
#pragma unroll
        for (int q = 0; q < 6; q++) {
            float4 v  = row[lane + q*32];
            float4 wv = swr[lane + q*32];
            d += v.x*wv.x + v.y*wv.y + v.z*wv.z + v.w*wv.w;
        }
#pragma unroll
        for (int o = 16; o; o >>= 1) d += __shfl_xor_sync(0xffffffffu, d, o);
        if (lane == 0) sg[i - i0] = 1.f / (1.f + __expf(-(d + brv)));
    }
    __syncthreads();

    const float4* base = lb + t;
    bf16* outp = g_nf + ((size_t)(b * NN + ng * NPG)) * HH + t*4;
#pragma unroll 1
    for (int n = 0; n < NPG; n++) {
        int j0 = ssoff[n] - i0, j1 = ssoff[n+1] - i0;
        int cnt = j1 - j0;
        float inv = 1.f / (float)(cnt < 1 ? 1 : cnt);
        float ax = 0.f, ay = 0.f, az = 0.f, aw = 0.f;
        int i = j0;
        for (; i + 4 <= j1; i += 4) {
            float4 v0 = base[(size_t)sperm[i+0] * 192];
            float4 v1 = base[(size_t)sperm[i+1] * 192];
            float4 v2 = base[(size_t)sperm[i+2] * 192];
            float4 v3 = base[(size_t)sperm[i+3] * 192];
            float w0 = sg[i+0], w1 = sg[i+1], w2 = sg[i+2], w3 = sg[i+3];
            ax += w0*v0.x; ay += w0*v0.y; az += w0*v0.z; aw += w0*v0.w;
            ax += w1*v1.x; ay += w1*v1.y; az += w1*v1.z; aw += w1*v1.w;
            ax += w2*v2.x; ay += w2*v2.y; az += w2*v2.z; aw += w2*v2.w;
            ax += w3*v3.x; ay += w3*v3.y; az += w3*v3.z; aw += w3*v3.w;
        }
        for (; i < j1; i++) {
            float4 v = base[(size_t)sperm[i] * 192];
            float ww = sg[i];
            ax += ww*v.x; ay += ww*v.y; az += ww*v.z; aw += ww*v.w;
        }
        __nv_bfloat162 o0 = __floats2bfloat162_rn(ax*inv, ay*inv);
        __nv_bfloat162 o1 = __floats2bfloat162_rn(az*inv, aw*inv);
        *(__nv_bfloat162*)(outp + (size_t)n*HH)     = o0;
        *(__nv_bfloat162*)(outp + (size_t)n*HH + 2) = o1;
    }
}

// ---------------- K4/K6 (slot 4 PROFILED): Yt = (X @ Wt^T)^T, BM=32/BN=64 ---------
// grid (BNN/32, 2), 128 threads = 4 warps (2m x 2n), warp tile 16x32.
template<int KD, int SEL>
__global__ __launch_bounds__(128)
void k_gemm_tc() {
    const bf16* __restrict__ X  = SEL ? g_X1  : g_nf;
    const bf16* __restrict__ Wt = SEL ? g_W2t : g_W1t;
    bf16* __restrict__ Yt       = SEL ? g_H2t : g_H1t;
    __shared__ bf16 As[4][32][40];
    __shared__ bf16 Bs[4][64][40];
    int m0 = blockIdx.x * 32, n0 = blockIdx.y * 64;
    int t = threadIdx.x, lane = t & 31, warp = t >> 5;
    int gid = lane >> 2, tig = lane & 3;
    int wm = (warp & 1) * 16, wn = (warp >> 1) * 32;
    int aRa = t >> 2, aHa = (t & 3) * 8;    // A: 32 rows x 32 cols, 1 cp16/thread
    int aRb = t >> 1, aHb = (t & 1) * 16;   // B: 64 rows x 32 cols, 2 cp16/thread

    const bf16* Xr = X  + (size_t)(m0 + aRa)*KD + aHa;
    const bf16* Wr = Wt + (size_t)(n0 + aRb)*KD + aHb;

    float acc[4][4];
#pragma unroll
    for (int j = 0; j < 4; j++)
#pragma unroll
        for (int q = 0; q < 4; q++) acc[j][q] = 0.f;

    const int NIT = KD / 32;

#define GEMM_ISSUE(ii) do {                                              \
        int st_ = (ii) & 3; int k0_ = (ii) * 32;                         \
        uint32_t sa_ = (uint32_t)__cvta_generic_to_shared(&As[st_][aRa][aHa]); \
        uint32_t sb_ = (uint32_t)__cvta_generic_to_shared(&Bs[st_][aRb][aHb]); \
        cp16(sa_,      Xr + k0_);                                        \
        cp16(sb_,      Wr + k0_);                                        \
        cp16(sb_ + 16, Wr + k0_ + 8);                                    \
        cp_commit();                                                     \
    } while (0)

    GEMM_ISSUE(0); GEMM_ISSUE(1); GEMM_ISSUE(2);

    for (int i = 0; i < NIT; i++) {
        cp_wait2();
        __syncthreads();
        if (i + 3 < NIT) GEMM_ISSUE(i + 3);
        else cp_commit();                 // tail-safe accounting
        mma_tile32(As[i & 3], Bs[i & 3], acc, wm, wn, gid, tig);
    }
#undef GEMM_ISSUE

    // transposed epilogue through smem: tile [32 m][68 n]
    __syncthreads();
    bf16* tp = &As[0][0][0];
#pragma unroll
    for (int j = 0; j < 4; j++) {
        int r = wm + gid, cc = wn + j*8 + 2*tig;
        *(__nv_bfloat162*)&tp[r*68 + cc]     = __floats2bfloat162_rn(acc[j][0], acc[j][1]);
        *(__nv_bfloat162*)&tp[(r+8)*68 + cc] = __floats2bfloat162_rn(acc[j][2], acc[j][3]);
    }
    __syncthreads();
    int bb = m0 >> 7, nodeBase = m0 & 127;
    int rw = t >> 1, hf = (t & 1) * 16;
    bf16* outp = Yt + ((size_t)bb*GHD + n0 + rw) * NN + nodeBase + hf;
#pragma unroll
    for (int q = 0; q < 2; q++) {
        bf16 e[8];
#pragma unroll
        for (int k = 0; k < 8; k++) e[k] = tp[(hf + q*8 + k)*68 + rw];
        *(uint4*)&outp[q*8] = *(uint4*)e;
    }
}

// ---------------- K5/K7: relu(A_b @ H_b + bias), BM=32; POOL -> column mean ------
// grid (8, BB): mt = bx & 3 (32-node tiles), nt = bx >> 2 (64-feat tiles).
template<bool POOL>
__global__ __launch_bounds__(128)
void k_gcn_agg(const float* __restrict__ bias) {
    const bf16* __restrict__ Ht = POOL ? g_H2t : g_H1t;
    __shared__ bf16 As[4][32][40];
    __shared__ bf16 Bs[4][64][40];
    __shared__ float sred[64];
    int mt = blockIdx.x & 3, nt = blockIdx.x >> 2;
    int b = blockIdx.y;
    int t = threadIdx.x, lane = t & 31, warp = t >> 5;
    int gid = lane >> 2, tig = lane & 3;
    int wm = (warp & 1) * 16, wn = (warp >> 1) * 32;
    int aRa = t >> 2, aHa = (t & 3) * 8;
    int aRb = t >> 1, aHb = (t & 1) * 16;

    if (POOL && t < 64) sred[t] = 0.f;

    const bf16* Ar = g_A + (size_t)b*NN*NN  + (size_t)(mt*32 + aRa)*NN + aHa;
    const bf16* Br = Ht  + (size_t)b*GHD*NN + (size_t)(nt*64 + aRb)*NN + aHb;

    float acc[4][4];
#pragma unroll
    for (int j = 0; j < 4; j++)
#pragma unroll
        for (int q = 0; q < 4; q++) acc[j][q] = 0.f;

    const int NIT = NN / 32;   // 4

#define AGG_ISSUE(ii) do {                                               \
        int st_ = (ii) & 3; int k0_ = (ii) * 32;                         \
        uint32_t sa_ = (uint32_t)__cvta_generic_to_shared(&As[st_][aRa][aHa]); \
        uint32_t sb_ = (uint32_t)__cvta_generic_to_shared(&Bs[st_][aRb][aHb]); \
        cp16(sa_,      Ar + k0_);                                        \
        cp16(sb_,      Br + k0_);                                        \
        cp16(sb_ + 16, Br + k0_ + 8);                                    \
        cp_commit();                                                     \
    } while (0)

    AGG_ISSUE(0); AGG_ISSUE(1); AGG_ISSUE(2);

    for (int i = 0; i < NIT; i++) {
        cp_wait2();
        __syncthreads();
        if (i + 3 < NIT) AGG_ISSUE(i + 3);
        else cp_commit();                 // tail-safe accounting
        mma_tile32(As[i & 3], Bs[i & 3], acc, wm, wn, gid, tig);
    }
#undef AGG_ISSUE

    if (POOL) {
        float cs[4][2];
#pragma unroll
        for (int j = 0; j < 4; j++) { cs[j][0] = 0.f; cs[j][1] = 0.f; }
#pragma unroll
        for (int j = 0; j < 4; j++) {
            int cG = nt*64 + wn + j*8 + 2*tig;
            float b0 = bias[cG], b1 = bias[cG+1];
            cs[j][0] += fmaxf(acc[j][0] + b0, 0.f) + fmaxf(acc[j][2] + b0, 0.f);
            cs[j][1] += fmaxf(acc[j][1] + b1, 0.f) + fmaxf(acc[j][3] + b1, 0.f);
        }
#pragma unroll
        for (int off = 4; off <= 16; off <<= 1)
#pragma unroll
            for (int j = 0; j < 4; j++) {
                cs[j][0] += __shfl_xor_sync(0xffffffffu, cs[j][0], off);
                cs[j][1] += __shfl_xor_sync(0xffffffffu, cs[j][1], off);
            }
        __syncthreads();   // sred init visible
        if (gid == 0) {
#pragma unroll
            for (int j = 0; j < 4; j++) {
                atomicAdd(&sred[wn + j*8 + 2*tig],     cs[j][0]);
                atomicAdd(&sred[wn + j*8 + 2*tig + 1], cs[j][1]);
            }
        }
        __syncthreads();
        if (t < 64)
            atomicAdd(&g_pooled[b*GHD + nt*64 + t], sred[t] * (1.f/128.f));
    } else {
#pragma unroll
        for (int j = 0; j < 4; j++) {
            int rnode = mt*32 + wm + gid;
            int cG = nt*64 + wn + j*8 + 2*tig;
            float b0 = bias[cG], b1 = bias[cG+1];
            float v00 = fmaxf(acc[j][0] + b0, 0.f);
            float v01 = fmaxf(acc[j][1] + b1, 0.f);
            float v10 = fmaxf(acc[j][2] + b0, 0.f);
            float v11 = fmaxf(acc[j][3] + b1, 0.f);
            *(__nv_bfloat162*)&g_X1[((size_t)(b*NN + rnode))*GHD + cG]     = __floats2bfloat162_rn(v00, v01);
            *(__nv_bfloat162*)&g_X1[((size_t)(b*NN + rnode + 8))*GHD + cG] = __floats2bfloat162_rn(v10, v11);
        }
    }
}

// ---------------- K8: MLP head ----------------
__global__ __launch_bounds__(256)
void k_head(const float* __restrict__ lh, const float* __restrict__ Wf1,
            const float* __restrict__ bf1, const float* __restrict__ Wf2,
            const float* __restrict__ bf2, float* __restrict__ out) {
    __shared__ float xin[HH + GHD];
    __shared__ float sh[FHD];
    int b = blockIdx.x, t = threadIdx.x;   // 256
    for (int i = t; i < HH; i += 256) xin[i] = lh[((size_t)b*SS)*HH + i];
    if (t < GHD) xin[HH + t] = g_pooled[b*GHD + t];
    __syncthreads();
    float a0 = 0.f, a1 = 0.f, a2 = 0.f, a3 = 0.f;
    for (int k = 0; k < HH + GHD; k += 4) {
        a0 += xin[k+0] * Wf1[(k+0)*FHD + t];
        a1 += xin[k+1] * Wf1[(k+1)*FHD + t];
        a2 += xin[k+2] * Wf1[(k+2)*FHD + t];
        a3 += xin[k+3] * Wf1[(k+3)*FHD + t];
    }
    sh[t] = fmaxf(a0 + a1 + a2 + a3 + bf1[t], 0.f);
    __syncthreads();
    int w = t >> 5, lane = t & 31;
    if (w < 2) {
        float s = 0.f;
        for (int k = lane; k < FHD; k += 32) s += sh[k] * Wf2[k*2 + w];
#pragma unroll
        for (int o = 16; o; o >>= 1) s += __shfl_xor_sync(0xffffffffu, s, o);
        if (lane == 0) out[b*2 + w] = s + bf2[w];
    }
}

// ---------------- launch: ONLY kernel launches ----------------
extern "C" void kernel_launch(void* const* d_in, const int* in_sizes, int n_in,
                              void* d_out, int out_size) {
    const float* lh     = (const float*)d_in[0];
    const int*   submap = (const int*)  d_in[1];
    const int*   ei     = (const int*)  d_in[2];
    // d_in[3] = num_nodes (always 128, unused)
    const float* wr  = (const float*)d_in[4];
    const float* br  = (const float*)d_in[5];
    const float* W1  = (const float*)d_in[6];
    const float* b1  = (const float*)d_in[7];
    const float* W2  = (const float*)d_in[8];
    const float* b2  = (const float*)d_in[9];
    const float* Wf1 = (const float*)d_in[10];
    const float* bf1 = (const float*)d_in[11];
    const float* Wf2 = (const float*)d_in[12];
    const float* bf2 = (const float*)d_in[13];
    float* out = (float*)d_out;

    k_sortc<<<BB, 128>>>(submap);                           // 1
    k_prepWz<<<(HH*GHD + GHD*GHD + BB*GHD + 255)/256, 256>>>(W1, W2); // 2
    dim3 gsa(NGRP + 2, BB);                                 // scatter groups + adj halves
    k_scatadj<<<gsa, 192>>>(lh, wr, br, ei);                // 3
    dim3 gg1(BNN/32, 2);                                    // 512 CTAs
    k_gemm_tc<HH, 0><<<gg1, 128>>>();                       // 4 <- profiled slot
    dim3 gag(8, BB);                                        // 512 CTAs
    k_gcn_agg<false><<<gag, 128>>>(b1);                     // 5
    dim3 gg2(BNN/32, 2);
    k_gemm_tc<GHD, 1><<<gg2, 128>>>();                      // 6
    k_gcn_agg<true><<<gag, 128>>>(b2);                      // 7
    k_head<<<BB, 256>>>(lh, Wf1, bf1, Wf2, bf2, out);       // 8
}